// round 1
// baseline (speedup 1.0000x reference)
#include <cuda_runtime.h>
#include <cuda_bf16.h>
#include <math.h>

#define Bn 8
#define Tn 1024
#define Cn 2048
#define Hn 32
#define Nn 64
#define BT (Bn*Tn)                 // 8192
#define BTC ((size_t)BT*Cn)        // 16777216
#define LN_EPS (1e-5f*64.0f)

// ---------------- scratch (static device globals; no allocation) ----------------
__device__ float g_xr[BTC], g_xw[BTC], g_xk[BTC], g_xv[BTC], g_xa[BTC], g_xg[BTC];
__device__ float g_r[BTC], g_k[BTC], g_v[BTC], g_wz[BTC], g_a[BTC], g_vg[BTC];
__device__ float g_g[BTC], g_kk[BTC], g_knew[BTC], g_y[BTC], g_yg[BTC];
__device__ float g_h1[(size_t)BT*128];

// ---------------- elementwise: token-shift mixing ----------------
__global__ void mix_kernel(const float* __restrict__ x, const float* __restrict__ mask,
                           const float* __restrict__ mr, const float* __restrict__ mw,
                           const float* __restrict__ mk, const float* __restrict__ mv,
                           const float* __restrict__ ma, const float* __restrict__ mg)
{
    size_t i = (size_t)blockIdx.x * blockDim.x + threadIdx.x;
    if (i >= BTC) return;
    int c = (int)(i % Cn);
    size_t bt = i / Cn;
    int t = (int)(bt % Tn);
    float m  = mask[bt];
    float xm = x[i] * m;
    float xp = 0.f;
    if (t > 0) xp = x[i - Cn] * mask[bt - 1];
    float xx = xp - xm;
    g_xr[i] = xm + xx * mr[c];
    g_xw[i] = xm + xx * mw[c];
    g_xk[i] = xm + xx * mk[c];
    g_xv[i] = xm + xx * mv[c];
    g_xa[i] = xm + xx * ma[c];
    g_xg[i] = xm + xx * mg[c];
}

// ---------------- big GEMM: C[m,n] = sum_k A[m,k] * B[n,k]  (NT) ----------------
__global__ __launch_bounds__(256)
void sgemm_nt(const float* __restrict__ A, const float* __restrict__ B,
              float* __restrict__ Cm, int M, int Nc, int K)
{
    __shared__ float As[8][128];
    __shared__ float Bs[8][128];
    const int bm = blockIdx.y * 128, bn = blockIdx.x * 128;
    const int tid = threadIdx.x;
    const int lr = tid >> 1, lc = (tid & 1) * 4;
    const int m0 = (tid >> 4) * 8, n0 = (tid & 15) * 8;
    float acc[8][8];
#pragma unroll
    for (int i = 0; i < 8; i++)
#pragma unroll
        for (int j = 0; j < 8; j++) acc[i][j] = 0.f;

    const float* Ap = A + (size_t)(bm + lr) * K + lc;
    const float* Bp = B + (size_t)(bn + lr) * K + lc;

    for (int k0 = 0; k0 < K; k0 += 8) {
        float4 av = *(const float4*)(Ap + k0);
        float4 bv = *(const float4*)(Bp + k0);
        As[lc + 0][lr] = av.x; As[lc + 1][lr] = av.y; As[lc + 2][lr] = av.z; As[lc + 3][lr] = av.w;
        Bs[lc + 0][lr] = bv.x; Bs[lc + 1][lr] = bv.y; Bs[lc + 2][lr] = bv.z; Bs[lc + 3][lr] = bv.w;
        __syncthreads();
#pragma unroll
        for (int k = 0; k < 8; k++) {
            float rm[8], rn[8];
#pragma unroll
            for (int i = 0; i < 8; i++) rm[i] = As[k][m0 + i];
#pragma unroll
            for (int j = 0; j < 8; j++) rn[j] = Bs[k][n0 + j];
#pragma unroll
            for (int i = 0; i < 8; i++)
#pragma unroll
                for (int j = 0; j < 8; j++) acc[i][j] = fmaf(rm[i], rn[j], acc[i][j]);
        }
        __syncthreads();
    }
#pragma unroll
    for (int i = 0; i < 8; i++)
#pragma unroll
        for (int j = 0; j < 8; j++)
            Cm[(size_t)(bm + m0 + i) * Nc + bn + n0 + j] = acc[i][j];
}

// ---------------- small GEMM 1: [M,K=2048] @ [K,Nd] (NN), Nd in {64,96,128} ----------------
// block: (Nd, 8) threads, BM=32 rows, BK=64
template<int ND, int ACT>  // ACT: 0 none, 1 tanh, 2 sigmoid
__global__ void mlp1_kernel(const float* __restrict__ A, const float* __restrict__ B,
                            float* __restrict__ Out, int K)
{
    __shared__ float As[32][64];
    __shared__ float Bs[64][ND];
    const int tx = threadIdx.x, ty = threadIdx.y;
    const int tid = ty * ND + tx;
    const int nth = ND * 8;
    const int m0 = blockIdx.x * 32;
    float acc[4] = {0.f, 0.f, 0.f, 0.f};

    for (int k0 = 0; k0 < K; k0 += 64) {
        for (int idx = tid; idx < 32 * 64; idx += nth) {
            int r = idx >> 6, cc = idx & 63;
            As[r][cc] = A[(size_t)(m0 + r) * K + k0 + cc];
        }
        for (int idx = tid; idx < 64 * ND; idx += nth) {
            int kk = idx / ND, n = idx % ND;
            Bs[kk][n] = B[(size_t)(k0 + kk) * ND + n];
        }
        __syncthreads();
#pragma unroll 8
        for (int kk = 0; kk < 64; kk++) {
            float bv = Bs[kk][tx];
            acc[0] = fmaf(As[ty][kk],      bv, acc[0]);
            acc[1] = fmaf(As[ty + 8][kk],  bv, acc[1]);
            acc[2] = fmaf(As[ty + 16][kk], bv, acc[2]);
            acc[3] = fmaf(As[ty + 24][kk], bv, acc[3]);
        }
        __syncthreads();
    }
#pragma unroll
    for (int i = 0; i < 4; i++) {
        float v = acc[i];
        if (ACT == 1) v = tanhf(v);
        else if (ACT == 2) v = 1.f / (1.f + expf(-v));
        Out[(size_t)(m0 + ty + 8 * i) * ND + tx] = v;
    }
}

// ---------------- small GEMM 2: [M,K<=128] @ [K, 2048] (NN) ----------------
// MODE: 0 none, 1 sigmoid(bias+x), 2 bias+x
template<int MODE>
__global__ __launch_bounds__(256)
void mlp2_kernel(const float* __restrict__ A, const float* __restrict__ B,
                 const float* __restrict__ bias, float* __restrict__ Out, int K)
{
    __shared__ float As[32][33];
    __shared__ float Bs[32][64];
    const int tid = threadIdx.x;
    const int tx = tid & 15, ty = tid >> 4;   // ty 0..15
    const int m0 = blockIdx.y * 32, n0 = blockIdx.x * 64;
    float acc[2][4] = {{0.f,0.f,0.f,0.f},{0.f,0.f,0.f,0.f}};

    for (int k0 = 0; k0 < K; k0 += 32) {
        for (int idx = tid; idx < 32 * 32; idx += 256) {
            int r = idx >> 5, cc = idx & 31;
            As[r][cc] = A[(size_t)(m0 + r) * K + k0 + cc];
        }
        for (int idx = tid; idx < 32 * 64; idx += 256) {
            int kk = idx >> 6, n = idx & 63;
            Bs[kk][n] = B[(size_t)(k0 + kk) * Cn + n0 + n];
        }
        __syncthreads();
#pragma unroll 8
        for (int kk = 0; kk < 32; kk++) {
            float a0v = As[ty][kk], a1v = As[ty + 16][kk];
#pragma unroll
            for (int j = 0; j < 4; j++) {
                float bv = Bs[kk][tx * 4 + j];
                acc[0][j] = fmaf(a0v, bv, acc[0][j]);
                acc[1][j] = fmaf(a1v, bv, acc[1][j]);
            }
        }
        __syncthreads();
    }
#pragma unroll
    for (int i = 0; i < 2; i++)
#pragma unroll
        for (int j = 0; j < 4; j++) {
            int m = m0 + ty + 16 * i, n = n0 + tx * 4 + j;
            float v = acc[i][j];
            if (MODE == 1) v = 1.f / (1.f + expf(-(bias[n] + v)));
            else if (MODE == 2) v = bias[n] + v;
            Out[(size_t)m * Cn + n] = v;
        }
}

// ---------------- v combine: v = v + (vf - v)*gate ; v *= mask ----------------
__global__ void vcombine_kernel(const float* __restrict__ vf, const float* __restrict__ mask)
{
    size_t i = (size_t)blockIdx.x * blockDim.x + threadIdx.x;
    if (i >= BTC) return;
    float v = g_v[i];
    float gate = g_vg[i];
    v = v + (vf[i] - v) * gate;
    g_v[i] = v * mask[i / Cn];
}

// ---------------- kk normalize + k update ----------------
__global__ void kk_kernel(const float* __restrict__ kkw, const float* __restrict__ kaw)
{
    int gid = blockIdx.x;             // (b*T + t)*H + h
    int h = gid & (Hn - 1);
    int lane = threadIdx.x;
    size_t base = (size_t)gid * 64;
    int c0 = h * 64 + lane, c1 = c0 + 32;

    float k0v = g_k[base + lane], k1v = g_k[base + lane + 32];
    float kk0 = k0v * kkw[c0], kk1 = k1v * kkw[c1];
    float ss = kk0 * kk0 + kk1 * kk1;
#pragma unroll
    for (int off = 16; off > 0; off >>= 1) ss += __shfl_xor_sync(0xffffffffu, ss, off);
    float inv = 1.f / fmaxf(sqrtf(ss), 1e-12f);
    g_kk[base + lane] = kk0 * inv;
    g_kk[base + lane + 32] = kk1 * inv;

    float a0v = g_a[base + lane], a1v = g_a[base + lane + 32];
    g_knew[base + lane]      = k0v * (1.f + (a0v - 1.f) * kaw[c0]);
    g_knew[base + lane + 32] = k1v * (1.f + (a1v - 1.f) * kaw[c1]);
}

// ---------------- RWKV-7 sequential scan: one block per (b,h), 64 threads ----------------
__global__ __launch_bounds__(64)
void scan_kernel()
{
    const int bh = blockIdx.x;                 // b*H + h
    const int b = bh / Hn, h = bh % Hn;
    const int j = threadIdx.x;
    size_t base = (size_t)b * Tn * Cn + h * 64;

    float S[64];
#pragma unroll
    for (int i = 0; i < 64; i++) S[i] = 0.f;

    __shared__ float rs[64], ws[64], ks[64], vs[64], as_[64], bs_[64];

    for (int t = 0; t < Tn; t++) {
        size_t idx = base + (size_t)t * Cn + j;
        rs[j] = g_r[idx];
        float z = g_wz[idx];
        // wdec = exp(-exp(w)) with w = -softplus(-z)-0.5  =>  exp(w) = e^{-1/2} * sigmoid(z)
        ws[j] = expf(-0.60653066f / (1.f + expf(-z)));
        ks[j] = g_knew[idx];
        vs[j] = g_v[idx];
        float kkv = g_kk[idx];
        as_[j] = -kkv;
        bs_[j] = kkv * g_a[idx];
        __syncthreads();

        float sa = 0.f;
#pragma unroll
        for (int i = 0; i < 64; i++) sa = fmaf(S[i], as_[i], sa);

        float vj = vs[j], yj = 0.f;
#pragma unroll
        for (int i = 0; i < 64; i++) {
            float s = fmaf(S[i], ws[i], fmaf(sa, bs_[i], vj * ks[i]));
            S[i] = s;
            yj = fmaf(s, rs[i], yj);
        }
        g_y[idx] = yj;
        __syncthreads();
    }
}

// ---------------- groupnorm + rk*v bonus + gate multiply ----------------
__global__ __launch_bounds__(128)
void postln_kernel(const float* __restrict__ rkw, const float* __restrict__ lnw,
                   const float* __restrict__ lnb)
{
    const int warp = threadIdx.x >> 5, lane = threadIdx.x & 31;
    const int gid = blockIdx.x * 4 + warp;     // (b*T + t)*H + h
    const int h = gid & (Hn - 1);
    size_t base = (size_t)gid * 64;
    int c0 = h * 64 + lane, c1 = c0 + 32;

    float y0 = g_y[base + lane], y1 = g_y[base + lane + 32];
    float s = y0 + y1;
#pragma unroll
    for (int off = 16; off > 0; off >>= 1) s += __shfl_xor_sync(0xffffffffu, s, off);
    float mu = s * (1.f / 64.f);
    float d0 = y0 - mu, d1 = y1 - mu;
    float vs = d0 * d0 + d1 * d1;
#pragma unroll
    for (int off = 16; off > 0; off >>= 1) vs += __shfl_xor_sync(0xffffffffu, vs, off);
    float inv = rsqrtf(vs * (1.f / 64.f) + LN_EPS);

    float rk = g_r[base + lane] * g_knew[base + lane] * rkw[c0]
             + g_r[base + lane + 32] * g_knew[base + lane + 32] * rkw[c1];
#pragma unroll
    for (int off = 16; off > 0; off >>= 1) rk += __shfl_xor_sync(0xffffffffu, rk, off);

    float yn0 = d0 * inv * lnw[c0] + lnb[c0];
    float yn1 = d1 * inv * lnw[c1] + lnb[c1];
    g_yg[base + lane]      = (yn0 + rk * g_v[base + lane])      * g_g[base + lane];
    g_yg[base + lane + 32] = (yn1 + rk * g_v[base + lane + 32]) * g_g[base + lane + 32];
}

// ---------------- host ----------------
static float* sym(const void* s) { void* p = nullptr; cudaGetSymbolAddress(&p, s); return (float*)p; }

extern "C" void kernel_launch(void* const* d_in, const int* in_sizes, int n_in,
                              void* d_out, int out_size)
{
    const float* x    = (const float*)d_in[0];
    const float* mask = (const float*)d_in[1];
    const float* vf   = (const float*)d_in[2];
    const float* x_r  = (const float*)d_in[3];
    const float* x_w  = (const float*)d_in[4];
    const float* x_k  = (const float*)d_in[5];
    const float* x_v  = (const float*)d_in[6];
    const float* x_a  = (const float*)d_in[7];
    const float* x_g  = (const float*)d_in[8];
    const float* w0   = (const float*)d_in[9];
    const float* w1   = (const float*)d_in[10];
    const float* w2   = (const float*)d_in[11];
    const float* a0   = (const float*)d_in[12];
    const float* a1   = (const float*)d_in[13];
    const float* a2   = (const float*)d_in[14];
    const float* v0   = (const float*)d_in[15];
    const float* v1   = (const float*)d_in[16];
    const float* v2   = (const float*)d_in[17];
    const float* g1   = (const float*)d_in[18];
    const float* g2   = (const float*)d_in[19];
    const float* k_k  = (const float*)d_in[20];
    const float* k_a  = (const float*)d_in[21];
    const float* r_k  = (const float*)d_in[22];
    const float* W_r  = (const float*)d_in[23];
    const float* W_k  = (const float*)d_in[24];
    const float* W_v  = (const float*)d_in[25];
    const float* W_o  = (const float*)d_in[26];
    const float* ln_w = (const float*)d_in[27];
    const float* ln_b = (const float*)d_in[28];

    float* p_xr = sym(g_xr); float* p_xw = sym(g_xw); float* p_xk = sym(g_xk);
    float* p_xv = sym(g_xv); float* p_xa = sym(g_xa); float* p_xg = sym(g_xg);
    float* p_r = sym(g_r); float* p_k = sym(g_k); float* p_v = sym(g_v);
    float* p_wz = sym(g_wz); float* p_a = sym(g_a); float* p_vg = sym(g_vg);
    float* p_g = sym(g_g); float* p_yg = sym(g_yg); float* p_h1 = sym(g_h1);

    float* out = (float*)d_out;

    // 1) token shift + mixing
    mix_kernel<<<(unsigned)((BTC + 255) / 256), 256>>>(x, mask, x_r, x_w, x_k, x_v, x_a, x_g);

    // 2) big projections r/k/v
    dim3 gg(Cn / 128, BT / 128);
    sgemm_nt<<<gg, 256>>>(p_xr, W_r, p_r, BT, Cn, Cn);
    sgemm_nt<<<gg, 256>>>(p_xk, W_k, p_k, BT, Cn, Cn);
    sgemm_nt<<<gg, 256>>>(p_xv, W_v, p_v, BT, Cn, Cn);

    // 3) w MLP (tanh, then z = w0 + h@w2)
    mlp1_kernel<96, 1><<<BT / 32, dim3(96, 8)>>>(p_xw, w1, p_h1, Cn);
    mlp2_kernel<2><<<dim3(Cn / 64, BT / 32), 256>>>(p_h1, w2, w0, p_wz, 96);

    // 4) a MLP (sigmoid(a0 + .))
    mlp1_kernel<96, 0><<<BT / 32, dim3(96, 8)>>>(p_xa, a1, p_h1, Cn);
    mlp2_kernel<1><<<dim3(Cn / 64, BT / 32), 256>>>(p_h1, a2, a0, p_a, 96);

    // 5) v gate MLP (sigmoid(v0 + .)), then combine with v_first
    mlp1_kernel<64, 0><<<BT / 32, dim3(64, 8)>>>(p_xv, v1, p_h1, Cn);
    mlp2_kernel<1><<<dim3(Cn / 64, BT / 32), 256>>>(p_h1, v2, v0, p_vg, 64);
    vcombine_kernel<<<(unsigned)((BTC + 255) / 256), 256>>>(vf, mask);

    // 6) g MLP (sigmoid at hidden, no output activation)
    mlp1_kernel<128, 2><<<BT / 32, dim3(128, 8)>>>(p_xg, g1, p_h1, Cn);
    mlp2_kernel<0><<<dim3(Cn / 64, BT / 32), 256>>>(p_h1, g2, nullptr, p_g, 128);

    // 7) kk normalize + k update
    kk_kernel<<<BT * Hn, 32>>>(k_k, k_a);

    // 8) sequential scan
    scan_kernel<<<Bn * Hn, 64>>>();

    // 9) groupnorm + rk bonus + gate
    postln_kernel<<<BT * Hn / 4, 128>>>(r_k, ln_w, ln_b);

    // 10) output projection
    sgemm_nt<<<gg, 256>>>(p_yg, W_o, out, BT, Cn, Cn);

    // 11) second output = v_first passthrough (if harness expects both outputs)
    if ((size_t)out_size >= 2 * BTC) {
        cudaMemcpyAsync(out + BTC, vf, BTC * sizeof(float), cudaMemcpyDeviceToDevice, 0);
    }
}

// round 2
// speedup vs baseline: 1.5645x; 1.5645x over previous
#include <cuda_runtime.h>
#include <cuda_bf16.h>
#include <math.h>
#include <stdint.h>

#define Bn 8
#define Tn 1024
#define Cn 2048
#define Hn 32
#define Nn 64
#define BT (Bn*Tn)                 // 8192
#define BTC ((size_t)BT*Cn)        // 16777216
#define LN_EPS (1e-5f*64.0f)
#define KT_TILES 192               // 6144/32

// ---------------- scratch (static device globals; no allocation) ----------------
__device__ float g_xr[BTC], g_xw[BTC], g_xk[BTC], g_xv[BTC], g_xa[BTC], g_xg[BTC];
__device__ float g_r[BTC], g_k[BTC], g_v[BTC], g_wz[BTC], g_a[BTC], g_vg[BTC];
__device__ float g_g[BTC], g_kk[BTC], g_knew[BTC], g_y[BTC], g_yg[BTC];
__device__ float g_h1[(size_t)BT*128];
__device__ __nv_bfloat16 g_Abf[(size_t)BT*4096];        // [M][hi 2048 | lo 2048]
__device__ __nv_bfloat16 g_Wbf[4][(size_t)Cn*4096];     // per weight: [N][hi | lo]

// ---------------- elementwise: token-shift mixing ----------------
__global__ void mix_kernel(const float* __restrict__ x, const float* __restrict__ mask,
                           const float* __restrict__ mr, const float* __restrict__ mw,
                           const float* __restrict__ mk, const float* __restrict__ mv,
                           const float* __restrict__ ma, const float* __restrict__ mg)
{
    size_t i = (size_t)blockIdx.x * blockDim.x + threadIdx.x;
    if (i >= BTC) return;
    int c = (int)(i % Cn);
    size_t bt = i / Cn;
    int t = (int)(bt % Tn);
    float m  = mask[bt];
    float xm = x[i] * m;
    float xp = 0.f;
    if (t > 0) xp = x[i - Cn] * mask[bt - 1];
    float xx = xp - xm;
    g_xr[i] = xm + xx * mr[c];
    g_xw[i] = xm + xx * mw[c];
    g_xk[i] = xm + xx * mk[c];
    g_xv[i] = xm + xx * mv[c];
    g_xa[i] = xm + xx * ma[c];
    g_xg[i] = xm + xx * mg[c];
}

// ---------------- split fp32 -> (hi, lo) bf16 ----------------
__global__ void conv_split(const float* __restrict__ src, __nv_bfloat16* __restrict__ dst,
                           int rows)
{
    size_t i = (size_t)blockIdx.x * blockDim.x + threadIdx.x;
    size_t n = (size_t)rows * Cn;
    if (i >= n) return;
    size_t row = i / Cn, c = i % Cn;
    float x = src[i];
    __nv_bfloat16 hi = __float2bfloat16(x);
    __nv_bfloat16 lo = __float2bfloat16(x - __bfloat162float(hi));
    dst[row * 4096 + c] = hi;
    dst[row * 4096 + 2048 + c] = lo;
}

// ---------------- split-bf16 tensor-core GEMM: C = A @ B^T (fp32-accurate) ----------------
// A [M][4096] (hi|lo), B [N][4096] (hi|lo). Virtual K = 6144 covering
// A_hi*B_hi + A_lo*B_hi + A_hi*B_lo.
__global__ __launch_bounds__(256, 2)
void hgemm_split(const __nv_bfloat16* __restrict__ A, const __nv_bfloat16* __restrict__ Bw,
                 float* __restrict__ Cm)
{
    __shared__ __nv_bfloat16 As[2][128 * 40];
    __shared__ __nv_bfloat16 Bs[2][128 * 40];
    const int tid = threadIdx.x;
    const int bm = blockIdx.y * 128, bn = blockIdx.x * 128;
    const int w = tid >> 5, lane = tid & 31;
    const int wm = (w & 3) * 32, wn = (w >> 2) * 64;

    float acc[2][8][4];
#pragma unroll
    for (int mi = 0; mi < 2; mi++)
#pragma unroll
        for (int ni = 0; ni < 8; ni++)
#pragma unroll
            for (int q = 0; q < 4; q++) acc[mi][ni][q] = 0.f;

    auto loadtile = [&](int stage, int t) {
        int aoff = (t < 128) ? t * 32 : t * 32 - 4096;
        int boff = (t < 64) ? t * 32 : t * 32 - 2048;
#pragma unroll
        for (int c = 0; c < 2; c++) {
            int ch = tid + c * 256;        // 0..511
            int row = ch >> 2, col = ch & 3;
            unsigned sa = (unsigned)__cvta_generic_to_shared(&As[stage][row * 40 + col * 8]);
            const void* ga = &A[(size_t)(bm + row) * 4096 + aoff + col * 8];
            asm volatile("cp.async.cg.shared.global [%0], [%1], 16;\n" :: "r"(sa), "l"(ga));
            unsigned sb = (unsigned)__cvta_generic_to_shared(&Bs[stage][row * 40 + col * 8]);
            const void* gb = &Bw[(size_t)(bn + row) * 4096 + boff + col * 8];
            asm volatile("cp.async.cg.shared.global [%0], [%1], 16;\n" :: "r"(sb), "l"(gb));
        }
        asm volatile("cp.async.commit_group;\n" ::: "memory");
    };

    loadtile(0, 0);

    for (int t = 0; t < KT_TILES; t++) {
        if (t + 1 < KT_TILES) {
            loadtile((t + 1) & 1, t + 1);
            asm volatile("cp.async.wait_group 1;\n" ::: "memory");
        } else {
            asm volatile("cp.async.wait_group 0;\n" ::: "memory");
        }
        __syncthreads();

        const __nv_bfloat16* as = As[t & 1];
        const __nv_bfloat16* bs = Bs[t & 1];
#pragma unroll
        for (int kk = 0; kk < 32; kk += 16) {
            const int kq = kk + (lane & 3) * 2;
            uint32_t afr[2][4];
#pragma unroll
            for (int mi = 0; mi < 2; mi++) {
                int rb = wm + mi * 16 + (lane >> 2);
                afr[mi][0] = *(const uint32_t*)&as[rb * 40 + kq];
                afr[mi][1] = *(const uint32_t*)&as[(rb + 8) * 40 + kq];
                afr[mi][2] = *(const uint32_t*)&as[rb * 40 + kq + 8];
                afr[mi][3] = *(const uint32_t*)&as[(rb + 8) * 40 + kq + 8];
            }
#pragma unroll
            for (int ni = 0; ni < 8; ni++) {
                int nb = wn + ni * 8 + (lane >> 2);
                uint32_t b0 = *(const uint32_t*)&bs[nb * 40 + kq];
                uint32_t b1 = *(const uint32_t*)&bs[nb * 40 + kq + 8];
#pragma unroll
                for (int mi = 0; mi < 2; mi++) {
                    float* c = acc[mi][ni];
                    asm volatile(
                        "mma.sync.aligned.m16n8k16.row.col.f32.bf16.bf16.f32 "
                        "{%0,%1,%2,%3}, {%4,%5,%6,%7}, {%8,%9}, {%0,%1,%2,%3};\n"
                        : "+f"(c[0]), "+f"(c[1]), "+f"(c[2]), "+f"(c[3])
                        : "r"(afr[mi][0]), "r"(afr[mi][1]), "r"(afr[mi][2]), "r"(afr[mi][3]),
                          "r"(b0), "r"(b1));
                }
            }
        }
        __syncthreads();
    }

#pragma unroll
    for (int mi = 0; mi < 2; mi++)
#pragma unroll
        for (int ni = 0; ni < 8; ni++) {
            int row = bm + wm + mi * 16 + (lane >> 2);
            int col = bn + wn + ni * 8 + (lane & 3) * 2;
            Cm[(size_t)row * Cn + col]     = acc[mi][ni][0];
            Cm[(size_t)row * Cn + col + 1] = acc[mi][ni][1];
            Cm[(size_t)(row + 8) * Cn + col]     = acc[mi][ni][2];
            Cm[(size_t)(row + 8) * Cn + col + 1] = acc[mi][ni][3];
        }
}

// ---------------- small GEMM 1: [M,K=2048] @ [K,Nd] (NN) ----------------
template<int ND, int ACT>  // ACT: 0 none, 1 tanh, 2 sigmoid
__global__ void mlp1_kernel(const float* __restrict__ A, const float* __restrict__ B,
                            float* __restrict__ Out, int K)
{
    __shared__ float As[32][64];
    __shared__ float Bs[64][ND];
    const int tx = threadIdx.x, ty = threadIdx.y;
    const int tid = ty * ND + tx;
    const int nth = ND * 8;
    const int m0 = blockIdx.x * 32;
    float acc[4] = {0.f, 0.f, 0.f, 0.f};

    for (int k0 = 0; k0 < K; k0 += 64) {
        for (int idx = tid; idx < 32 * 64; idx += nth) {
            int r = idx >> 6, cc = idx & 63;
            As[r][cc] = A[(size_t)(m0 + r) * K + k0 + cc];
        }
        for (int idx = tid; idx < 64 * ND; idx += nth) {
            int kk = idx / ND, n = idx % ND;
            Bs[kk][n] = B[(size_t)(k0 + kk) * ND + n];
        }
        __syncthreads();
#pragma unroll 8
        for (int kk = 0; kk < 64; kk++) {
            float bv = Bs[kk][tx];
            acc[0] = fmaf(As[ty][kk],      bv, acc[0]);
            acc[1] = fmaf(As[ty + 8][kk],  bv, acc[1]);
            acc[2] = fmaf(As[ty + 16][kk], bv, acc[2]);
            acc[3] = fmaf(As[ty + 24][kk], bv, acc[3]);
        }
        __syncthreads();
    }
#pragma unroll
    for (int i = 0; i < 4; i++) {
        float v = acc[i];
        if (ACT == 1) v = tanhf(v);
        else if (ACT == 2) v = 1.f / (1.f + expf(-v));
        Out[(size_t)(m0 + ty + 8 * i) * ND + tx] = v;
    }
}

// ---------------- small GEMM 2: [M,K<=128] @ [K, 2048] (NN) ----------------
template<int MODE>  // 0 none, 1 sigmoid(bias+x), 2 bias+x
__global__ __launch_bounds__(256)
void mlp2_kernel(const float* __restrict__ A, const float* __restrict__ B,
                 const float* __restrict__ bias, float* __restrict__ Out, int K)
{
    __shared__ float As[32][33];
    __shared__ float Bs[32][64];
    const int tid = threadIdx.x;
    const int tx = tid & 15, ty = tid >> 4;
    const int m0 = blockIdx.y * 32, n0 = blockIdx.x * 64;
    float acc[2][4] = {{0.f,0.f,0.f,0.f},{0.f,0.f,0.f,0.f}};

    for (int k0 = 0; k0 < K; k0 += 32) {
        for (int idx = tid; idx < 32 * 32; idx += 256) {
            int r = idx >> 5, cc = idx & 31;
            As[r][cc] = A[(size_t)(m0 + r) * K + k0 + cc];
        }
        for (int idx = tid; idx < 32 * 64; idx += 256) {
            int kk = idx >> 6, n = idx & 63;
            Bs[kk][n] = B[(size_t)(k0 + kk) * Cn + n0 + n];
        }
        __syncthreads();
#pragma unroll 8
        for (int kk = 0; kk < 32; kk++) {
            float a0v = As[ty][kk], a1v = As[ty + 16][kk];
#pragma unroll
            for (int j = 0; j < 4; j++) {
                float bv = Bs[kk][tx * 4 + j];
                acc[0][j] = fmaf(a0v, bv, acc[0][j]);
                acc[1][j] = fmaf(a1v, bv, acc[1][j]);
            }
        }
        __syncthreads();
    }
#pragma unroll
    for (int i = 0; i < 2; i++)
#pragma unroll
        for (int j = 0; j < 4; j++) {
            int m = m0 + ty + 16 * i, n = n0 + tx * 4 + j;
            float v = acc[i][j];
            if (MODE == 1) v = 1.f / (1.f + expf(-(bias[n] + v)));
            else if (MODE == 2) v = bias[n] + v;
            Out[(size_t)m * Cn + n] = v;
        }
}

// ---------------- v combine ----------------
__global__ void vcombine_kernel(const float* __restrict__ vf, const float* __restrict__ mask)
{
    size_t i = (size_t)blockIdx.x * blockDim.x + threadIdx.x;
    if (i >= BTC) return;
    float v = g_v[i];
    float gate = g_vg[i];
    v = v + (vf[i] - v) * gate;
    g_v[i] = v * mask[i / Cn];
}

// ---------------- kk normalize + k update ----------------
__global__ void kk_kernel(const float* __restrict__ kkw, const float* __restrict__ kaw)
{
    int gid = blockIdx.x;
    int h = gid & (Hn - 1);
    int lane = threadIdx.x;
    size_t base = (size_t)gid * 64;
    int c0 = h * 64 + lane, c1 = c0 + 32;

    float k0v = g_k[base + lane], k1v = g_k[base + lane + 32];
    float kk0 = k0v * kkw[c0], kk1 = k1v * kkw[c1];
    float ss = kk0 * kk0 + kk1 * kk1;
#pragma unroll
    for (int off = 16; off > 0; off >>= 1) ss += __shfl_xor_sync(0xffffffffu, ss, off);
    float inv = 1.f / fmaxf(sqrtf(ss), 1e-12f);
    g_kk[base + lane] = kk0 * inv;
    g_kk[base + lane + 32] = kk1 * inv;

    float a0v = g_a[base + lane], a1v = g_a[base + lane + 32];
    g_knew[base + lane]      = k0v * (1.f + (a0v - 1.f) * kaw[c0]);
    g_knew[base + lane + 32] = k1v * (1.f + (a1v - 1.f) * kaw[c1]);
}

// ---------------- RWKV-7 scan ----------------
__global__ __launch_bounds__(64)
void scan_kernel()
{
    const int bh = blockIdx.x;
    const int b = bh / Hn, h = bh % Hn;
    const int j = threadIdx.x;
    size_t base = (size_t)b * Tn * Cn + h * 64;

    float S[64];
#pragma unroll
    for (int i = 0; i < 64; i++) S[i] = 0.f;

    __shared__ float rs[64], ws[64], ks[64], vs[64], as_[64], bs_[64];

    for (int t = 0; t < Tn; t++) {
        size_t idx = base + (size_t)t * Cn + j;
        rs[j] = g_r[idx];
        float z = g_wz[idx];
        ws[j] = expf(-0.60653066f / (1.f + expf(-z)));
        ks[j] = g_knew[idx];
        vs[j] = g_v[idx];
        float kkv = g_kk[idx];
        as_[j] = -kkv;
        bs_[j] = kkv * g_a[idx];
        __syncthreads();

        float sa = 0.f;
#pragma unroll
        for (int i = 0; i < 64; i++) sa = fmaf(S[i], as_[i], sa);

        float vj = vs[j], yj = 0.f;
#pragma unroll
        for (int i = 0; i < 64; i++) {
            float s = fmaf(S[i], ws[i], fmaf(sa, bs_[i], vj * ks[i]));
            S[i] = s;
            yj = fmaf(s, rs[i], yj);
        }
        g_y[idx] = yj;
        __syncthreads();
    }
}

// ---------------- groupnorm + rk*v bonus + gate ----------------
__global__ __launch_bounds__(128)
void postln_kernel(const float* __restrict__ rkw, const float* __restrict__ lnw,
                   const float* __restrict__ lnb)
{
    const int warp = threadIdx.x >> 5, lane = threadIdx.x & 31;
    const int gid = blockIdx.x * 4 + warp;
    const int h = gid & (Hn - 1);
    size_t base = (size_t)gid * 64;
    int c0 = h * 64 + lane, c1 = c0 + 32;

    float y0 = g_y[base + lane], y1 = g_y[base + lane + 32];
    float s = y0 + y1;
#pragma unroll
    for (int off = 16; off > 0; off >>= 1) s += __shfl_xor_sync(0xffffffffu, s, off);
    float mu = s * (1.f / 64.f);
    float d0 = y0 - mu, d1 = y1 - mu;
    float vs = d0 * d0 + d1 * d1;
#pragma unroll
    for (int off = 16; off > 0; off >>= 1) vs += __shfl_xor_sync(0xffffffffu, vs, off);
    float inv = rsqrtf(vs * (1.f / 64.f) + LN_EPS);

    float rk = g_r[base + lane] * g_knew[base + lane] * rkw[c0]
             + g_r[base + lane + 32] * g_knew[base + lane + 32] * rkw[c1];
#pragma unroll
    for (int off = 16; off > 0; off >>= 1) rk += __shfl_xor_sync(0xffffffffu, rk, off);

    float yn0 = d0 * inv * lnw[c0] + lnb[c0];
    float yn1 = d1 * inv * lnw[c1] + lnb[c1];
    g_yg[base + lane]      = (yn0 + rk * g_v[base + lane])      * g_g[base + lane];
    g_yg[base + lane + 32] = (yn1 + rk * g_v[base + lane + 32]) * g_g[base + lane + 32];
}

// ---------------- host ----------------
static float* sym(const void* s) { void* p = nullptr; cudaGetSymbolAddress(&p, s); return (float*)p; }
static __nv_bfloat16* symb(const void* s) { void* p = nullptr; cudaGetSymbolAddress(&p, s); return (__nv_bfloat16*)p; }

extern "C" void kernel_launch(void* const* d_in, const int* in_sizes, int n_in,
                              void* d_out, int out_size)
{
    const float* x    = (const float*)d_in[0];
    const float* mask = (const float*)d_in[1];
    const float* vf   = (const float*)d_in[2];
    const float* x_r  = (const float*)d_in[3];
    const float* x_w  = (const float*)d_in[4];
    const float* x_k  = (const float*)d_in[5];
    const float* x_v  = (const float*)d_in[6];
    const float* x_a  = (const float*)d_in[7];
    const float* x_g  = (const float*)d_in[8];
    const float* w0   = (const float*)d_in[9];
    const float* w1   = (const float*)d_in[10];
    const float* w2   = (const float*)d_in[11];
    const float* a0   = (const float*)d_in[12];
    const float* a1   = (const float*)d_in[13];
    const float* a2   = (const float*)d_in[14];
    const float* v0   = (const float*)d_in[15];
    const float* v1   = (const float*)d_in[16];
    const float* v2   = (const float*)d_in[17];
    const float* g1   = (const float*)d_in[18];
    const float* g2   = (const float*)d_in[19];
    const float* k_k  = (const float*)d_in[20];
    const float* k_a  = (const float*)d_in[21];
    const float* r_k  = (const float*)d_in[22];
    const float* W_r  = (const float*)d_in[23];
    const float* W_k  = (const float*)d_in[24];
    const float* W_v  = (const float*)d_in[25];
    const float* W_o  = (const float*)d_in[26];
    const float* ln_w = (const float*)d_in[27];
    const float* ln_b = (const float*)d_in[28];

    float* p_xr = sym(g_xr); float* p_xw = sym(g_xw); float* p_xk = sym(g_xk);
    float* p_xv = sym(g_xv); float* p_xa = sym(g_xa); float* p_xg = sym(g_xg);
    float* p_r = sym(g_r); float* p_k = sym(g_k); float* p_v = sym(g_v);
    float* p_wz = sym(g_wz); float* p_a = sym(g_a); float* p_vg = sym(g_vg);
    float* p_g = sym(g_g); float* p_yg = sym(g_yg); float* p_h1 = sym(g_h1);
    __nv_bfloat16* p_Abf = symb(g_Abf);
    __nv_bfloat16* p_Wbf = symb(g_Wbf);

    float* out = (float*)d_out;

    const unsigned EW = (unsigned)((BTC + 255) / 256);
    const unsigned WW = (unsigned)(((size_t)Cn * Cn + 255) / 256);
    dim3 gg(Cn / 128, BT / 128);

    // 0) convert the four big weights to split-bf16
    conv_split<<<WW, 256>>>(W_r, p_Wbf + 0 * (size_t)Cn * 4096, Cn);
    conv_split<<<WW, 256>>>(W_k, p_Wbf + 1 * (size_t)Cn * 4096, Cn);
    conv_split<<<WW, 256>>>(W_v, p_Wbf + 2 * (size_t)Cn * 4096, Cn);
    conv_split<<<WW, 256>>>(W_o, p_Wbf + 3 * (size_t)Cn * 4096, Cn);

    // 1) token shift + mixing
    mix_kernel<<<EW, 256>>>(x, mask, x_r, x_w, x_k, x_v, x_a, x_g);

    // 2) big projections r/k/v on tensor cores (split-bf16)
    conv_split<<<EW, 256>>>(p_xr, p_Abf, BT);
    hgemm_split<<<gg, 256>>>(p_Abf, p_Wbf + 0 * (size_t)Cn * 4096, p_r);
    conv_split<<<EW, 256>>>(p_xk, p_Abf, BT);
    hgemm_split<<<gg, 256>>>(p_Abf, p_Wbf + 1 * (size_t)Cn * 4096, p_k);
    conv_split<<<EW, 256>>>(p_xv, p_Abf, BT);
    hgemm_split<<<gg, 256>>>(p_Abf, p_Wbf + 2 * (size_t)Cn * 4096, p_v);

    // 3) w MLP
    mlp1_kernel<96, 1><<<BT / 32, dim3(96, 8)>>>(p_xw, w1, p_h1, Cn);
    mlp2_kernel<2><<<dim3(Cn / 64, BT / 32), 256>>>(p_h1, w2, w0, p_wz, 96);

    // 4) a MLP
    mlp1_kernel<96, 0><<<BT / 32, dim3(96, 8)>>>(p_xa, a1, p_h1, Cn);
    mlp2_kernel<1><<<dim3(Cn / 64, BT / 32), 256>>>(p_h1, a2, a0, p_a, 96);

    // 5) v gate MLP + combine
    mlp1_kernel<64, 0><<<BT / 32, dim3(64, 8)>>>(p_xv, v1, p_h1, Cn);
    mlp2_kernel<1><<<dim3(Cn / 64, BT / 32), 256>>>(p_h1, v2, v0, p_vg, 64);
    vcombine_kernel<<<EW, 256>>>(vf, mask);

    // 6) g MLP
    mlp1_kernel<128, 2><<<BT / 32, dim3(128, 8)>>>(p_xg, g1, p_h1, Cn);
    mlp2_kernel<0><<<dim3(Cn / 64, BT / 32), 256>>>(p_h1, g2, nullptr, p_g, 128);

    // 7) kk normalize + k update
    kk_kernel<<<BT * Hn, 32>>>(k_k, k_a);

    // 8) sequential scan
    scan_kernel<<<Bn * Hn, 64>>>();

    // 9) groupnorm + rk bonus + gate
    postln_kernel<<<BT * Hn / 4, 128>>>(r_k, ln_w, ln_b);

    // 10) output projection on tensor cores
    conv_split<<<EW, 256>>>(p_yg, p_Abf, BT);
    hgemm_split<<<gg, 256>>>(p_Abf, p_Wbf + 3 * (size_t)Cn * 4096, out);

    // 11) second output = v_first passthrough
    if ((size_t)out_size >= 2 * BTC) {
        cudaMemcpyAsync(out + BTC, vf, BTC * sizeof(float), cudaMemcpyDeviceToDevice, 0);
    }
}

// round 3
// speedup vs baseline: 2.1650x; 1.3839x over previous
#include <cuda_runtime.h>
#include <cuda_bf16.h>
#include <math.h>
#include <stdint.h>

#define Bn 8
#define Tn 1024
#define Cn 2048
#define Hn 32
#define BT (Bn*Tn)                 // 8192
#define BTC ((size_t)BT*Cn)        // 16777216
#define LN_EPS (1e-5f*64.0f)
#define KP 128                     // padded small-K

typedef __nv_bfloat16 bf16;

// ---------------- scratch ----------------
__device__ float g_r[BTC], g_k[BTC], g_v[BTC], g_wdec[BTC], g_a[BTC], g_vg[BTC];
__device__ float g_g[BTC], g_nkk[BTC], g_ab[BTC], g_knew[BTC], g_y[BTC];
__device__ bf16 g_xr[(size_t)BT*4096], g_xw[(size_t)BT*4096], g_xk[(size_t)BT*4096];
__device__ bf16 g_xv[(size_t)BT*4096], g_xa[(size_t)BT*4096], g_xg[(size_t)BT*4096];
__device__ bf16 g_ygbf[(size_t)BT*4096];
__device__ bf16 g_Wbf[4][(size_t)Cn*4096];
__device__ bf16 g_w1t[4][(size_t)KP*4096];     // [128][4096] hi|lo, rows>=ND zero
__device__ bf16 g_w2t[4][(size_t)Cn*2*KP];     // [2048][256] hi|lo, cols k>=ND zero
__device__ bf16 g_hid[(size_t)BT*2*KP];        // [8192][256] hi|lo

// ---------------- helpers ----------------
__device__ __forceinline__ void split_store(bf16* dst, size_t hi_idx, size_t lo_off, float v) {
    bf16 hi = __float2bfloat16(v);
    bf16 lo = __float2bfloat16(v - __bfloat162float(hi));
    dst[hi_idx] = hi;
    dst[hi_idx + lo_off] = lo;
}

// ---------------- mixing: writes split-bf16 directly ----------------
__global__ void mix_split(const float* __restrict__ x, const float* __restrict__ mask,
                          const float* __restrict__ mr, const float* __restrict__ mw,
                          const float* __restrict__ mk, const float* __restrict__ mv,
                          const float* __restrict__ ma, const float* __restrict__ mg)
{
    size_t i = (size_t)blockIdx.x * blockDim.x + threadIdx.x;
    if (i >= BTC) return;
    int c = (int)(i % Cn);
    size_t bt = i / Cn;
    int t = (int)(bt % Tn);
    float m  = mask[bt];
    float xm = x[i] * m;
    float xp = 0.f;
    if (t > 0) xp = x[i - Cn] * mask[bt - 1];
    float xx = xp - xm;
    size_t o = bt * 4096 + c;
    split_store(g_xr, o, 2048, xm + xx * mr[c]);
    split_store(g_xw, o, 2048, xm + xx * mw[c]);
    split_store(g_xk, o, 2048, xm + xx * mk[c]);
    split_store(g_xv, o, 2048, xm + xx * mv[c]);
    split_store(g_xa, o, 2048, xm + xx * ma[c]);
    split_store(g_xg, o, 2048, xm + xx * mg[c]);
}

// ---------------- weight conversions ----------------
__global__ void conv_split(const float* __restrict__ src, bf16* __restrict__ dst, int rows)
{
    size_t i = (size_t)blockIdx.x * blockDim.x + threadIdx.x;
    size_t n = (size_t)rows * Cn;
    if (i >= n) return;
    size_t row = i / Cn, c = i % Cn;
    split_store(dst, row * 4096 + c, 2048, src[i]);
}

// mlp1 weight [2048][nd] -> [128][4096] transposed split (rows >= nd zero)
__global__ void tsplit1(const float* __restrict__ in, bf16* __restrict__ out, int nd)
{
    int i = blockIdx.x * blockDim.x + threadIdx.x;   // over 128*2048
    if (i >= KP * Cn) return;
    int n = i / Cn, k = i % Cn;
    float v = (n < nd) ? in[(size_t)k * nd + n] : 0.f;
    split_store(out, (size_t)n * 4096 + k, 2048, v);
}

// mlp2 weight [nd][2048] -> [2048][256] transposed split (cols k >= nd zero)
__global__ void tsplit2(const float* __restrict__ in, bf16* __restrict__ out, int nd)
{
    int i = blockIdx.x * blockDim.x + threadIdx.x;   // over 2048*128
    if (i >= Cn * KP) return;
    int n = i / KP, k = i % KP;
    float v = (k < nd) ? in[(size_t)k * Cn + n] : 0.f;
    split_store(out, (size_t)n * (2 * KP) + k, KP, v);
}

// ---------------- epilogue transforms ----------------
template<int EPI>
__device__ __forceinline__ float epi_f32(float v, const float* bias, int n) {
    if (EPI == 1) return expf(-0.60653066f / (1.f + expf(-(bias[n] + v))));   // decay
    if (EPI == 2) return 1.f / (1.f + expf(-(bias[n] + v)));                  // sigmoid+bias
    return v;
}
template<int EPI>
__device__ __forceinline__ float epi_act(float v) {
    if (EPI == 3) return tanhf(v);
    if (EPI == 4) return 1.f / (1.f + expf(-v));
    return v;
}

// ---------------- split-bf16 tensor-core NT GEMM ----------------
// C = A @ B^T with A [M][2*KA] (hi|lo), B [N][2*KA] (hi|lo).
// Virtual K = 3*KA: seg0 Ah*Bh, seg1 Al*Bh, seg2 Ah*Bl.
// EPI 0/1/2 -> fp32 out (ldc = ncols); EPI 3/4/5 -> activation + split bf16 out (stride 256).
template<int KA, int EPI>
__global__ __launch_bounds__(256, 2)
void hgemm(const bf16* __restrict__ A, const bf16* __restrict__ Bw,
           float* __restrict__ Cf, bf16* __restrict__ Cb,
           const float* __restrict__ bias, int ncols)
{
    constexpr int TPS = KA / 32;
    constexpr int KT  = 3 * TPS;
    __shared__ bf16 As[2][128 * 40];
    __shared__ bf16 Bs[2][128 * 40];
    const int tid = threadIdx.x;
    const int bm = blockIdx.y * 128, bn = blockIdx.x * 128;
    const int w = tid >> 5, lane = tid & 31;
    const int wm = (w & 3) * 32, wn = (w >> 2) * 64;

    float acc[2][8][4];
#pragma unroll
    for (int mi = 0; mi < 2; mi++)
#pragma unroll
        for (int ni = 0; ni < 8; ni++)
#pragma unroll
            for (int q = 0; q < 4; q++) acc[mi][ni][q] = 0.f;

    auto loadtile = [&](int stage, int t) {
        int seg = t / TPS, kk = (t % TPS) * 32;
        int aoff = (seg == 1 ? KA : 0) + kk;
        int boff = (seg == 2 ? KA : 0) + kk;
#pragma unroll
        for (int c = 0; c < 2; c++) {
            int ch = tid + c * 256;
            int row = ch >> 2, col = ch & 3;
            unsigned sa = (unsigned)__cvta_generic_to_shared(&As[stage][row * 40 + col * 8]);
            const void* ga = &A[(size_t)(bm + row) * (2 * KA) + aoff + col * 8];
            asm volatile("cp.async.cg.shared.global [%0], [%1], 16;\n" :: "r"(sa), "l"(ga));
            unsigned sb = (unsigned)__cvta_generic_to_shared(&Bs[stage][row * 40 + col * 8]);
            const void* gb = &Bw[(size_t)(bn + row) * (2 * KA) + boff + col * 8];
            asm volatile("cp.async.cg.shared.global [%0], [%1], 16;\n" :: "r"(sb), "l"(gb));
        }
        asm volatile("cp.async.commit_group;\n" ::: "memory");
    };

    loadtile(0, 0);

    for (int t = 0; t < KT; t++) {
        if (t + 1 < KT) {
            loadtile((t + 1) & 1, t + 1);
            asm volatile("cp.async.wait_group 1;\n" ::: "memory");
        } else {
            asm volatile("cp.async.wait_group 0;\n" ::: "memory");
        }
        __syncthreads();

        const bf16* as = As[t & 1];
        const bf16* bs = Bs[t & 1];
#pragma unroll
        for (int kk = 0; kk < 32; kk += 16) {
            const int kq = kk + (lane & 3) * 2;
            uint32_t afr[2][4];
#pragma unroll
            for (int mi = 0; mi < 2; mi++) {
                int rb = wm + mi * 16 + (lane >> 2);
                afr[mi][0] = *(const uint32_t*)&as[rb * 40 + kq];
                afr[mi][1] = *(const uint32_t*)&as[(rb + 8) * 40 + kq];
                afr[mi][2] = *(const uint32_t*)&as[rb * 40 + kq + 8];
                afr[mi][3] = *(const uint32_t*)&as[(rb + 8) * 40 + kq + 8];
            }
#pragma unroll
            for (int ni = 0; ni < 8; ni++) {
                int nb = wn + ni * 8 + (lane >> 2);
                uint32_t b0 = *(const uint32_t*)&bs[nb * 40 + kq];
                uint32_t b1 = *(const uint32_t*)&bs[nb * 40 + kq + 8];
#pragma unroll
                for (int mi = 0; mi < 2; mi++) {
                    float* c = acc[mi][ni];
                    asm volatile(
                        "mma.sync.aligned.m16n8k16.row.col.f32.bf16.bf16.f32 "
                        "{%0,%1,%2,%3}, {%4,%5,%6,%7}, {%8,%9}, {%0,%1,%2,%3};\n"
                        : "+f"(c[0]), "+f"(c[1]), "+f"(c[2]), "+f"(c[3])
                        : "r"(afr[mi][0]), "r"(afr[mi][1]), "r"(afr[mi][2]), "r"(afr[mi][3]),
                          "r"(b0), "r"(b1));
                }
            }
        }
        __syncthreads();
    }

#pragma unroll
    for (int mi = 0; mi < 2; mi++)
#pragma unroll
        for (int ni = 0; ni < 8; ni++) {
            int row = bm + wm + mi * 16 + (lane >> 2);
            int col = bn + wn + ni * 8 + (lane & 3) * 2;
            float* c = acc[mi][ni];
            if (col < ncols) {
                if (EPI <= 2) {
                    Cf[(size_t)row * ncols + col]           = epi_f32<EPI>(c[0], bias, col);
                    Cf[(size_t)row * ncols + col + 1]       = epi_f32<EPI>(c[1], bias, col + 1);
                    Cf[(size_t)(row + 8) * ncols + col]     = epi_f32<EPI>(c[2], bias, col);
                    Cf[(size_t)(row + 8) * ncols + col + 1] = epi_f32<EPI>(c[3], bias, col + 1);
                } else {
                    split_store(Cb, (size_t)row * 256 + col,           KP, epi_act<EPI>(c[0]));
                    split_store(Cb, (size_t)row * 256 + col + 1,       KP, epi_act<EPI>(c[1]));
                    split_store(Cb, (size_t)(row + 8) * 256 + col,     KP, epi_act<EPI>(c[2]));
                    split_store(Cb, (size_t)(row + 8) * 256 + col + 1, KP, epi_act<EPI>(c[3]));
                }
            }
        }
}

// ---------------- fused: v-combine + kk-normalize + k-update + scan precompute ----------------
__global__ __launch_bounds__(256)
void kkv_fused(const float* __restrict__ vf, const float* __restrict__ mask,
               const float* __restrict__ kkw, const float* __restrict__ kaw)
{
    const int warp = threadIdx.x >> 5, lane = threadIdx.x & 31;
    const int gid = blockIdx.x * 8 + warp;        // (bt)*H + h
    const int h = gid & (Hn - 1);
    const int bt = gid >> 5;
    size_t base = (size_t)gid * 64;
    int c0 = h * 64 + lane, c1 = c0 + 32;
    float m = mask[bt];

    // v combine
    float v0v = g_v[base + lane], v1v = g_v[base + lane + 32];
    float gt0 = g_vg[base + lane], gt1 = g_vg[base + lane + 32];
    v0v = (v0v + (vf[base + lane] - v0v) * gt0) * m;
    v1v = (v1v + (vf[base + lane + 32] - v1v) * gt1) * m;
    g_v[base + lane] = v0v;
    g_v[base + lane + 32] = v1v;

    // kk normalize + derived
    float k0v = g_k[base + lane], k1v = g_k[base + lane + 32];
    float kk0 = k0v * kkw[c0], kk1 = k1v * kkw[c1];
    float ss = kk0 * kk0 + kk1 * kk1;
#pragma unroll
    for (int off = 16; off > 0; off >>= 1) ss += __shfl_xor_sync(0xffffffffu, ss, off);
    float inv = 1.f / fmaxf(sqrtf(ss), 1e-12f);
    float a0v = g_a[base + lane], a1v = g_a[base + lane + 32];
    g_nkk[base + lane]      = -kk0 * inv;
    g_nkk[base + lane + 32] = -kk1 * inv;
    g_ab[base + lane]       = kk0 * inv * a0v;
    g_ab[base + lane + 32]  = kk1 * inv * a1v;
    g_knew[base + lane]      = k0v * (1.f + (a0v - 1.f) * kaw[c0]);
    g_knew[base + lane + 32] = k1v * (1.f + (a1v - 1.f) * kaw[c1]);
}

// ---------------- RWKV-7 scan with register prefetch ----------------
__global__ __launch_bounds__(64)
void scan_kernel()
{
    const int bh = blockIdx.x;
    const int b = bh / Hn, h = bh % Hn;
    const int j = threadIdx.x;
    size_t base = (size_t)b * Tn * Cn + h * 64;

    float S[64];
#pragma unroll
    for (int i = 0; i < 64; i++) S[i] = 0.f;

    __shared__ float rs[64], ws[64], ks[64], vs[64], as_[64], bs_[64];

    size_t idx = base + j;
    float pr = g_r[idx], pw = g_wdec[idx], pk = g_knew[idx];
    float pv = g_v[idx], pa = g_nkk[idx], pb = g_ab[idx];

    for (int t = 0; t < Tn; t++) {
        rs[j] = pr; ws[j] = pw; ks[j] = pk; vs[j] = pv; as_[j] = pa; bs_[j] = pb;
        __syncthreads();

        if (t + 1 < Tn) {
            size_t nx = base + (size_t)(t + 1) * Cn + j;
            pr = g_r[nx]; pw = g_wdec[nx]; pk = g_knew[nx];
            pv = g_v[nx]; pa = g_nkk[nx]; pb = g_ab[nx];
        }

        float sa = 0.f;
#pragma unroll
        for (int i = 0; i < 64; i++) sa = fmaf(S[i], as_[i], sa);

        float vj = vs[j], yj = 0.f;
#pragma unroll
        for (int i = 0; i < 64; i++) {
            float s = fmaf(S[i], ws[i], fmaf(sa, bs_[i], vj * ks[i]));
            S[i] = s;
            yj = fmaf(s, rs[i], yj);
        }
        g_y[base + (size_t)t * Cn + j] = yj;
        __syncthreads();
    }
}

// ---------------- groupnorm + rk bonus + gate -> split bf16 ----------------
__global__ __launch_bounds__(128)
void postln_kernel(const float* __restrict__ rkw, const float* __restrict__ lnw,
                   const float* __restrict__ lnb)
{
    const int warp = threadIdx.x >> 5, lane = threadIdx.x & 31;
    const int gid = blockIdx.x * 4 + warp;
    const int h = gid & (Hn - 1);
    const int bt = gid >> 5;
    size_t base = (size_t)gid * 64;
    int c0 = h * 64 + lane, c1 = c0 + 32;

    float y0 = g_y[base + lane], y1 = g_y[base + lane + 32];
    float s = y0 + y1;
#pragma unroll
    for (int off = 16; off > 0; off >>= 1) s += __shfl_xor_sync(0xffffffffu, s, off);
    float mu = s * (1.f / 64.f);
    float d0 = y0 - mu, d1 = y1 - mu;
    float vs = d0 * d0 + d1 * d1;
#pragma unroll
    for (int off = 16; off > 0; off >>= 1) vs += __shfl_xor_sync(0xffffffffu, vs, off);
    float inv = rsqrtf(vs * (1.f / 64.f) + LN_EPS);

    float rk = g_r[base + lane] * g_knew[base + lane] * rkw[c0]
             + g_r[base + lane + 32] * g_knew[base + lane + 32] * rkw[c1];
#pragma unroll
    for (int off = 16; off > 0; off >>= 1) rk += __shfl_xor_sync(0xffffffffu, rk, off);

    float yn0 = d0 * inv * lnw[c0] + lnb[c0];
    float yn1 = d1 * inv * lnw[c1] + lnb[c1];
    float o0 = (yn0 + rk * g_v[base + lane])      * g_g[base + lane];
    float o1 = (yn1 + rk * g_v[base + lane + 32]) * g_g[base + lane + 32];
    split_store(g_ygbf, (size_t)bt * 4096 + c0, 2048, o0);
    split_store(g_ygbf, (size_t)bt * 4096 + c1, 2048, o1);
}

// ---------------- host ----------------
template<typename T> static T* sym(const void* s) { void* p = nullptr; cudaGetSymbolAddress(&p, s); return (T*)p; }

extern "C" void kernel_launch(void* const* d_in, const int* in_sizes, int n_in,
                              void* d_out, int out_size)
{
    const float* x    = (const float*)d_in[0];
    const float* mask = (const float*)d_in[1];
    const float* vf   = (const float*)d_in[2];
    const float* x_r  = (const float*)d_in[3];
    const float* x_w  = (const float*)d_in[4];
    const float* x_k  = (const float*)d_in[5];
    const float* x_v  = (const float*)d_in[6];
    const float* x_a  = (const float*)d_in[7];
    const float* x_g  = (const float*)d_in[8];
    const float* w0   = (const float*)d_in[9];
    const float* w1   = (const float*)d_in[10];
    const float* w2   = (const float*)d_in[11];
    const float* a0   = (const float*)d_in[12];
    const float* a1   = (const float*)d_in[13];
    const float* a2   = (const float*)d_in[14];
    const float* v0   = (const float*)d_in[15];
    const float* v1   = (const float*)d_in[16];
    const float* v2   = (const float*)d_in[17];
    const float* g1   = (const float*)d_in[18];
    const float* g2   = (const float*)d_in[19];
    const float* k_k  = (const float*)d_in[20];
    const float* k_a  = (const float*)d_in[21];
    const float* r_k  = (const float*)d_in[22];
    const float* W_r  = (const float*)d_in[23];
    const float* W_k  = (const float*)d_in[24];
    const float* W_v  = (const float*)d_in[25];
    const float* W_o  = (const float*)d_in[26];
    const float* ln_w = (const float*)d_in[27];
    const float* ln_b = (const float*)d_in[28];

    float* p_r = sym<float>(g_r); float* p_v = sym<float>(g_v);
    float* p_wdec = sym<float>(g_wdec); float* p_a = sym<float>(g_a);
    float* p_vg = sym<float>(g_vg); float* p_g = sym<float>(g_g);
    float* p_kf = sym<float>(g_k);
    bf16* p_xr = sym<bf16>(g_xr); bf16* p_xw = sym<bf16>(g_xw);
    bf16* p_xk = sym<bf16>(g_xk); bf16* p_xv = sym<bf16>(g_xv);
    bf16* p_xa = sym<bf16>(g_xa); bf16* p_xg = sym<bf16>(g_xg);
    bf16* p_ygbf = sym<bf16>(g_ygbf);
    bf16* p_Wbf = sym<bf16>(g_Wbf);
    bf16* p_w1t = sym<bf16>(g_w1t);
    bf16* p_w2t = sym<bf16>(g_w2t);
    bf16* p_hid = sym<bf16>(g_hid);

    float* out = (float*)d_out;

    const unsigned EW = (unsigned)((BTC + 255) / 256);
    const unsigned WW = (unsigned)(((size_t)Cn * Cn + 255) / 256);
    const unsigned TW = (unsigned)((KP * Cn + 255) / 256);
    dim3 big(16, 64), mlp1g(1, 64);
    const size_t WS = (size_t)Cn * 4096;
    const size_t W1S = (size_t)KP * 4096;
    const size_t W2S = (size_t)Cn * 2 * KP;

    // weight prep
    conv_split<<<WW, 256>>>(W_r, p_Wbf + 0 * WS, Cn);
    conv_split<<<WW, 256>>>(W_k, p_Wbf + 1 * WS, Cn);
    conv_split<<<WW, 256>>>(W_v, p_Wbf + 2 * WS, Cn);
    conv_split<<<WW, 256>>>(W_o, p_Wbf + 3 * WS, Cn);
    tsplit1<<<TW, 256>>>(w1, p_w1t + 0 * W1S, 96);
    tsplit1<<<TW, 256>>>(a1, p_w1t + 1 * W1S, 96);
    tsplit1<<<TW, 256>>>(v1, p_w1t + 2 * W1S, 64);
    tsplit1<<<TW, 256>>>(g1, p_w1t + 3 * W1S, 128);
    tsplit2<<<TW, 256>>>(w2, p_w2t + 0 * W2S, 96);
    tsplit2<<<TW, 256>>>(a2, p_w2t + 1 * W2S, 96);
    tsplit2<<<TW, 256>>>(v2, p_w2t + 2 * W2S, 64);
    tsplit2<<<TW, 256>>>(g2, p_w2t + 3 * W2S, 128);

    // mixing (split-bf16 out)
    mix_split<<<EW, 256>>>(x, mask, x_r, x_w, x_k, x_v, x_a, x_g);

    // big projections
    hgemm<2048, 0><<<big, 256>>>(p_xr, p_Wbf + 0 * WS, p_r,  nullptr, nullptr, Cn);
    hgemm<2048, 0><<<big, 256>>>(p_xk, p_Wbf + 1 * WS, p_kf, nullptr, nullptr, Cn);
    hgemm<2048, 0><<<big, 256>>>(p_xv, p_Wbf + 2 * WS, p_v,  nullptr, nullptr, Cn);

    // w path: tanh hidden -> decay epilogue
    hgemm<2048, 3><<<mlp1g, 256>>>(p_xw, p_w1t + 0 * W1S, nullptr, p_hid, nullptr, 96);
    hgemm<128, 1><<<big, 256>>>(p_hid, p_w2t + 0 * W2S, p_wdec, nullptr, w0, Cn);
    // a path
    hgemm<2048, 5><<<mlp1g, 256>>>(p_xa, p_w1t + 1 * W1S, nullptr, p_hid, nullptr, 96);
    hgemm<128, 2><<<big, 256>>>(p_hid, p_w2t + 1 * W2S, p_a, nullptr, a0, Cn);
    // v gate path
    hgemm<2048, 5><<<mlp1g, 256>>>(p_xv, p_w1t + 2 * W1S, nullptr, p_hid, nullptr, 64);
    hgemm<128, 2><<<big, 256>>>(p_hid, p_w2t + 2 * W2S, p_vg, nullptr, v0, Cn);
    // g path
    hgemm<2048, 4><<<mlp1g, 256>>>(p_xg, p_w1t + 3 * W1S, nullptr, p_hid, nullptr, 128);
    hgemm<128, 0><<<big, 256>>>(p_hid, p_w2t + 3 * W2S, p_g, nullptr, nullptr, Cn);

    // fused v-combine + kk + scan precompute
    kkv_fused<<<BT * Hn / 8, 256>>>(vf, mask, k_k, k_a);

    // scan
    scan_kernel<<<Bn * Hn, 64>>>();

    // post groupnorm -> split bf16
    postln_kernel<<<BT * Hn / 4, 128>>>(r_k, ln_w, ln_b);

    // output projection
    hgemm<2048, 0><<<big, 256>>>(p_ygbf, p_Wbf + 3 * WS, out, nullptr, nullptr, Cn);

    if ((size_t)out_size >= 2 * BTC) {
        cudaMemcpyAsync(out + BTC, vf, BTC * sizeof(float), cudaMemcpyDeviceToDevice, 0);
    }
}

// round 5
// speedup vs baseline: 2.6949x; 1.2448x over previous
#include <cuda_runtime.h>
#include <cuda_bf16.h>
#include <math.h>
#include <stdint.h>

#define Bn 8
#define Tn 1024
#define Cn 2048
#define Hn 32
#define BT (Bn*Tn)                 // 8192
#define BTC ((size_t)BT*Cn)        // 16777216
#define LN_EPS (1e-5f*64.0f)
#define KP 128

typedef __nv_bfloat16 bf16;

// ---------------- scratch ----------------
__device__ float g_r[BTC], g_k[BTC], g_v[BTC], g_wdec[BTC], g_a[BTC], g_vg[BTC];
__device__ float g_g[BTC], g_nkk[BTC], g_ab[BTC], g_knew[BTC], g_y[BTC];
__device__ bf16 g_xr[(size_t)BT*4096], g_xw[(size_t)BT*4096], g_xk[(size_t)BT*4096];
__device__ bf16 g_xv[(size_t)BT*4096], g_xa[(size_t)BT*4096], g_xg[(size_t)BT*4096];
__device__ bf16 g_ygbf[(size_t)BT*4096];
__device__ bf16 g_Wbf[4][(size_t)Cn*4096];
__device__ bf16 g_w1t[4][(size_t)KP*4096];
__device__ bf16 g_w2t[4][(size_t)Cn*2*KP];
__device__ bf16 g_hid4[4][(size_t)BT*256];

// ---------------- helpers ----------------
__device__ __forceinline__ void split_store(bf16* dst, size_t hi_idx, size_t lo_off, float v) {
    bf16 hi = __float2bfloat16(v);
    bf16 lo = __float2bfloat16(v - __bfloat162float(hi));
    dst[hi_idx] = hi;
    dst[hi_idx + lo_off] = lo;
}

// ---------------- mixing ----------------
__global__ void mix_split(const float* __restrict__ x, const float* __restrict__ mask,
                          const float* __restrict__ mr, const float* __restrict__ mw,
                          const float* __restrict__ mk, const float* __restrict__ mv,
                          const float* __restrict__ ma, const float* __restrict__ mg)
{
    size_t i = (size_t)blockIdx.x * blockDim.x + threadIdx.x;
    if (i >= BTC) return;
    int c = (int)(i % Cn);
    size_t bt = i / Cn;
    int t = (int)(bt % Tn);
    float m  = mask[bt];
    float xm = x[i] * m;
    float xp = 0.f;
    if (t > 0) xp = x[i - Cn] * mask[bt - 1];
    float xx = xp - xm;
    size_t o = bt * 4096 + c;
    split_store(g_xr, o, 2048, xm + xx * mr[c]);
    split_store(g_xw, o, 2048, xm + xx * mw[c]);
    split_store(g_xk, o, 2048, xm + xx * mk[c]);
    split_store(g_xv, o, 2048, xm + xx * mv[c]);
    split_store(g_xa, o, 2048, xm + xx * ma[c]);
    split_store(g_xg, o, 2048, xm + xx * mg[c]);
}

// ---------------- weight conversions ----------------
__global__ void conv_split(const float* __restrict__ src, bf16* __restrict__ dst, int rows)
{
    size_t i = (size_t)blockIdx.x * blockDim.x + threadIdx.x;
    size_t n = (size_t)rows * Cn;
    if (i >= n) return;
    size_t row = i / Cn, c = i % Cn;
    split_store(dst, row * 4096 + c, 2048, src[i]);
}

__global__ void tsplit1(const float* __restrict__ in, bf16* __restrict__ out, int nd)
{
    int i = blockIdx.x * blockDim.x + threadIdx.x;
    if (i >= KP * Cn) return;
    int n = i / Cn, k = i % Cn;
    float v = (n < nd) ? in[(size_t)k * nd + n] : 0.f;
    split_store(out, (size_t)n * 4096 + k, 2048, v);
}

__global__ void tsplit2(const float* __restrict__ in, bf16* __restrict__ out, int nd)
{
    int i = blockIdx.x * blockDim.x + threadIdx.x;
    if (i >= Cn * KP) return;
    int n = i / KP, k = i % KP;
    float v = (k < nd) ? in[(size_t)k * Cn + n] : 0.f;
    split_store(out, (size_t)n * (2 * KP) + k, KP, v);
}

// ---------------- split-bf16 tensor-core NT GEMM core ----------------
// MODE 0: C = A @ B^T -> fp32 Cf (ncols=2048)
// MODE 6: batched mlp1 (z): A in {xw,xa,xv,xg}, B=w1t[z]; hidden act: z0 tanh, z3 sigmoid,
//         z1/z2 identity -> split bf16 hid4[z]
// MODE 7: batched mlp2 (z): A=hid4[z], B=w2t[z]; epilogue per z -> fp32 targets
template<int KA, int MODE>
__global__ __launch_bounds__(256, 2)
void hgemm(const bf16* __restrict__ Ain, const bf16* __restrict__ Bin,
           float* __restrict__ Cf, int ncols,
           const float* __restrict__ b0, const float* __restrict__ b1,
           const float* __restrict__ b2)
{
    constexpr int TPS = KA / 32;
    constexpr int KT  = 3 * TPS;
    constexpr int SSZ = 128 * 40;
    extern __shared__ bf16 sh[];
    bf16* As = sh;
    bf16* Bs = sh + 3 * SSZ;

    const int tid = threadIdx.x;
    const int z = blockIdx.z;
    const int bm = blockIdx.y * 128, bn = blockIdx.x * 128;
    const int w = tid >> 5, lane = tid & 31;
    const int wm = (w & 3) * 32, wn = (w >> 2) * 64;

    const bf16* A = Ain;
    const bf16* Bw = Bin;
    if (MODE == 6) {
        A = (z == 0) ? g_xw : (z == 1) ? g_xa : (z == 2) ? g_xv : g_xg;
        Bw = g_w1t[z];
    } else if (MODE == 7) {
        A = g_hid4[z];
        Bw = g_w2t[z];
    }

    float acc[2][8][4];
#pragma unroll
    for (int mi = 0; mi < 2; mi++)
#pragma unroll
        for (int ni = 0; ni < 8; ni++)
#pragma unroll
            for (int q = 0; q < 4; q++) acc[mi][ni][q] = 0.f;

    auto loadtile = [&](int stage, int t) {
        int seg = t / TPS, kk = (t % TPS) * 32;
        int aoff = (seg == 1 ? KA : 0) + kk;
        int boff = (seg == 2 ? KA : 0) + kk;
        bf16* as = As + stage * SSZ;
        bf16* bs = Bs + stage * SSZ;
#pragma unroll
        for (int c = 0; c < 2; c++) {
            int ch = tid + c * 256;
            int row = ch >> 2, col = ch & 3;
            unsigned sa = (unsigned)__cvta_generic_to_shared(&as[row * 40 + col * 8]);
            const void* ga = &A[(size_t)(bm + row) * (2 * KA) + aoff + col * 8];
            asm volatile("cp.async.cg.shared.global [%0], [%1], 16;\n" :: "r"(sa), "l"(ga));
            unsigned sb = (unsigned)__cvta_generic_to_shared(&bs[row * 40 + col * 8]);
            const void* gb = &Bw[(size_t)(bn + row) * (2 * KA) + boff + col * 8];
            asm volatile("cp.async.cg.shared.global [%0], [%1], 16;\n" :: "r"(sb), "l"(gb));
        }
        asm volatile("cp.async.commit_group;\n" ::: "memory");
    };

    loadtile(0, 0);
    loadtile(1, 1);

    const int arow = wm + (lane & 15);
    const int acolo = (lane >> 4) << 3;
    const int brow = (lane & 7) + ((lane & 16) ? 8 : 0);
    const int bcolo = (lane & 8) ? 8 : 0;

    for (int t = 0; t < KT; t++) {
        if (t + 1 < KT) {
            asm volatile("cp.async.wait_group 1;\n" ::: "memory");
        } else {
            asm volatile("cp.async.wait_group 0;\n" ::: "memory");
        }
        __syncthreads();
        if (t + 2 < KT) loadtile((t + 2) % 3, t + 2);

        const bf16* as = As + (t % 3) * SSZ;
        const bf16* bs = Bs + (t % 3) * SSZ;
        unsigned abase = (unsigned)__cvta_generic_to_shared(as);
        unsigned bbase = (unsigned)__cvta_generic_to_shared(bs);

#pragma unroll
        for (int kk = 0; kk < 32; kk += 16) {
            uint32_t af[2][4];
#pragma unroll
            for (int mi = 0; mi < 2; mi++) {
                unsigned aaddr = abase + (unsigned)(((arow + mi * 16) * 40 + kk + acolo) * 2);
                asm volatile("ldmatrix.sync.aligned.m8n8.x4.shared.b16 {%0,%1,%2,%3}, [%4];"
                             : "=r"(af[mi][0]), "=r"(af[mi][1]), "=r"(af[mi][2]), "=r"(af[mi][3])
                             : "r"(aaddr));
            }
            uint32_t bq[4][4];
#pragma unroll
            for (int n2 = 0; n2 < 4; n2++) {
                unsigned baddr = bbase + (unsigned)(((wn + n2 * 16 + brow) * 40 + kk + bcolo) * 2);
                asm volatile("ldmatrix.sync.aligned.m8n8.x4.shared.b16 {%0,%1,%2,%3}, [%4];"
                             : "=r"(bq[n2][0]), "=r"(bq[n2][1]), "=r"(bq[n2][2]), "=r"(bq[n2][3])
                             : "r"(baddr));
            }
#pragma unroll
            for (int n2 = 0; n2 < 4; n2++) {
#pragma unroll
                for (int mi = 0; mi < 2; mi++) {
                    float* c0 = acc[mi][2 * n2];
                    asm volatile(
                        "mma.sync.aligned.m16n8k16.row.col.f32.bf16.bf16.f32 "
                        "{%0,%1,%2,%3}, {%4,%5,%6,%7}, {%8,%9}, {%0,%1,%2,%3};\n"
                        : "+f"(c0[0]), "+f"(c0[1]), "+f"(c0[2]), "+f"(c0[3])
                        : "r"(af[mi][0]), "r"(af[mi][1]), "r"(af[mi][2]), "r"(af[mi][3]),
                          "r"(bq[n2][0]), "r"(bq[n2][1]));
                    float* c1 = acc[mi][2 * n2 + 1];
                    asm volatile(
                        "mma.sync.aligned.m16n8k16.row.col.f32.bf16.bf16.f32 "
                        "{%0,%1,%2,%3}, {%4,%5,%6,%7}, {%8,%9}, {%0,%1,%2,%3};\n"
                        : "+f"(c1[0]), "+f"(c1[1]), "+f"(c1[2]), "+f"(c1[3])
                        : "r"(af[mi][0]), "r"(af[mi][1]), "r"(af[mi][2]), "r"(af[mi][3]),
                          "r"(bq[n2][2]), "r"(bq[n2][3]));
                }
            }
        }
        __syncthreads();
    }

    // epilogue
#pragma unroll
    for (int mi = 0; mi < 2; mi++)
#pragma unroll
        for (int ni = 0; ni < 8; ni++) {
            int row = bm + wm + mi * 16 + (lane >> 2);
            int col = bn + wn + ni * 8 + (lane & 3) * 2;
            float* c = acc[mi][ni];
            if (MODE == 0) {
                Cf[(size_t)row * Cn + col]           = c[0];
                Cf[(size_t)row * Cn + col + 1]       = c[1];
                Cf[(size_t)(row + 8) * Cn + col]     = c[2];
                Cf[(size_t)(row + 8) * Cn + col + 1] = c[3];
            } else if (MODE == 6) {
                bf16* hid = g_hid4[z];
                // hidden activation: z0 = tanh (w path), z3 = sigmoid (g path),
                // z1/z2 (a, v-gate) = identity
                auto act = [&](float v) -> float {
                    if (z == 0) return tanhf(v);
                    if (z == 3) return 1.f / (1.f + expf(-v));
                    return v;
                };
                split_store(hid, (size_t)row * 256 + col,           KP, act(c[0]));
                split_store(hid, (size_t)row * 256 + col + 1,       KP, act(c[1]));
                split_store(hid, (size_t)(row + 8) * 256 + col,     KP, act(c[2]));
                split_store(hid, (size_t)(row + 8) * 256 + col + 1, KP, act(c[3]));
            } else {  // MODE 7
                float* dst = (z == 0) ? g_wdec : (z == 1) ? g_a : (z == 2) ? g_vg : g_g;
                auto epi = [&](float v, int n) -> float {
                    if (z == 0) return expf(-0.60653066f / (1.f + expf(-(b0[n] + v))));
                    if (z == 1) return 1.f / (1.f + expf(-(b1[n] + v)));
                    if (z == 2) return 1.f / (1.f + expf(-(b2[n] + v)));
                    return v;
                };
                dst[(size_t)row * Cn + col]           = epi(c[0], col);
                dst[(size_t)row * Cn + col + 1]       = epi(c[1], col + 1);
                dst[(size_t)(row + 8) * Cn + col]     = epi(c[2], col);
                dst[(size_t)(row + 8) * Cn + col + 1] = epi(c[3], col + 1);
            }
        }
}

// ---------------- fused: v-combine + kk-normalize + k-update ----------------
__global__ __launch_bounds__(256)
void kkv_fused(const float* __restrict__ vf, const float* __restrict__ mask,
               const float* __restrict__ kkw, const float* __restrict__ kaw)
{
    const int warp = threadIdx.x >> 5, lane = threadIdx.x & 31;
    const int gid = blockIdx.x * 8 + warp;
    const int h = gid & (Hn - 1);
    const int bt = gid >> 5;
    size_t base = (size_t)gid * 64;
    int c0 = h * 64 + lane, c1 = c0 + 32;
    float m = mask[bt];

    float v0v = g_v[base + lane], v1v = g_v[base + lane + 32];
    float gt0 = g_vg[base + lane], gt1 = g_vg[base + lane + 32];
    v0v = (v0v + (vf[base + lane] - v0v) * gt0) * m;
    v1v = (v1v + (vf[base + lane + 32] - v1v) * gt1) * m;
    g_v[base + lane] = v0v;
    g_v[base + lane + 32] = v1v;

    float k0v = g_k[base + lane], k1v = g_k[base + lane + 32];
    float kk0 = k0v * kkw[c0], kk1 = k1v * kkw[c1];
    float ss = kk0 * kk0 + kk1 * kk1;
#pragma unroll
    for (int off = 16; off > 0; off >>= 1) ss += __shfl_xor_sync(0xffffffffu, ss, off);
    float inv = 1.f / fmaxf(sqrtf(ss), 1e-12f);
    float a0v = g_a[base + lane], a1v = g_a[base + lane + 32];
    g_nkk[base + lane]      = -kk0 * inv;
    g_nkk[base + lane + 32] = -kk1 * inv;
    g_ab[base + lane]       = kk0 * inv * a0v;
    g_ab[base + lane + 32]  = kk1 * inv * a1v;
    g_knew[base + lane]      = k0v * (1.f + (a0v - 1.f) * kaw[c0]);
    g_knew[base + lane + 32] = k1v * (1.f + (a1v - 1.f) * kaw[c1]);
}

// ---------------- RWKV-7 scan: 128 threads, 2 per state row ----------------
__global__ __launch_bounds__(128)
void scan_kernel()
{
    const int bh = blockIdx.x;
    const int b = bh >> 5, h = bh & 31;
    const int tid = threadIdx.x;
    const int j = tid >> 1, half = tid & 1;
    size_t base = (size_t)b * Tn * Cn + h * 64;

    float S[32];
#pragma unroll
    for (int i = 0; i < 32; i++) S[i] = 0.f;

    __shared__ float sm[2][384];   // per buf: 0:r 64:w 128:k 192:v 256:nkk 320:ab

    const float* gsrc0;
    const float* gsrc1;
    const float* gsrc2;
    {
        const float* tbl[6] = {g_r, g_wdec, g_knew, g_v, g_nkk, g_ab};
        int l0 = tid, l1 = tid + 128, l2 = tid + 256;
        gsrc0 = tbl[l0 >> 6] + base + (l0 & 63);
        gsrc1 = tbl[l1 >> 6] + base + (l1 & 63);
        gsrc2 = tbl[l2 >> 6] + base + (l2 & 63);
    }
    float f0 = *gsrc0, f1 = *gsrc1, f2 = *gsrc2;

    for (int t = 0; t < Tn; t++) {
        float* sb = sm[t & 1];
        sb[tid] = f0; sb[tid + 128] = f1; sb[tid + 256] = f2;
        __syncthreads();

        if (t + 1 < Tn) {
            gsrc0 += Cn; gsrc1 += Cn; gsrc2 += Cn;
            f0 = *gsrc0; f1 = *gsrc1; f2 = *gsrc2;
        }

        const float* rv = sb + half * 32;
        const float* wv = sb + 64 + half * 32;
        const float* kv = sb + 128 + half * 32;
        const float* av = sb + 256 + half * 32;
        const float* bv = sb + 320 + half * 32;

        float sa = 0.f;
#pragma unroll
        for (int ii = 0; ii < 32; ii++) sa = fmaf(S[ii], av[ii], sa);
        sa += __shfl_xor_sync(0xffffffffu, sa, 1);

        float vj = sb[192 + j];
        float y = 0.f;
#pragma unroll
        for (int ii = 0; ii < 32; ii++) {
            float s = fmaf(S[ii], wv[ii], fmaf(sa, bv[ii], vj * kv[ii]));
            S[ii] = s;
            y = fmaf(s, rv[ii], y);
        }
        y += __shfl_xor_sync(0xffffffffu, y, 1);
        if (!half) g_y[base + (size_t)t * Cn + j] = y;
    }
}

// ---------------- groupnorm + rk bonus + gate -> split bf16 ----------------
__global__ __launch_bounds__(128)
void postln_kernel(const float* __restrict__ rkw, const float* __restrict__ lnw,
                   const float* __restrict__ lnb)
{
    const int warp = threadIdx.x >> 5, lane = threadIdx.x & 31;
    const int gid = blockIdx.x * 4 + warp;
    const int h = gid & (Hn - 1);
    const int bt = gid >> 5;
    size_t base = (size_t)gid * 64;
    int c0 = h * 64 + lane, c1 = c0 + 32;

    float y0 = g_y[base + lane], y1 = g_y[base + lane + 32];
    float s = y0 + y1;
#pragma unroll
    for (int off = 16; off > 0; off >>= 1) s += __shfl_xor_sync(0xffffffffu, s, off);
    float mu = s * (1.f / 64.f);
    float d0 = y0 - mu, d1 = y1 - mu;
    float vs = d0 * d0 + d1 * d1;
#pragma unroll
    for (int off = 16; off > 0; off >>= 1) vs += __shfl_xor_sync(0xffffffffu, vs, off);
    float inv = rsqrtf(vs * (1.f / 64.f) + LN_EPS);

    float rk = g_r[base + lane] * g_knew[base + lane] * rkw[c0]
             + g_r[base + lane + 32] * g_knew[base + lane + 32] * rkw[c1];
#pragma unroll
    for (int off = 16; off > 0; off >>= 1) rk += __shfl_xor_sync(0xffffffffu, rk, off);

    float yn0 = d0 * inv * lnw[c0] + lnb[c0];
    float yn1 = d1 * inv * lnw[c1] + lnb[c1];
    float o0 = (yn0 + rk * g_v[base + lane])      * g_g[base + lane];
    float o1 = (yn1 + rk * g_v[base + lane + 32]) * g_g[base + lane + 32];
    split_store(g_ygbf, (size_t)bt * 4096 + c0, 2048, o0);
    split_store(g_ygbf, (size_t)bt * 4096 + c1, 2048, o1);
}

// ---------------- host ----------------
template<typename T> static T* sym(const void* s) { void* p = nullptr; cudaGetSymbolAddress(&p, s); return (T*)p; }

extern "C" void kernel_launch(void* const* d_in, const int* in_sizes, int n_in,
                              void* d_out, int out_size)
{
    const float* x    = (const float*)d_in[0];
    const float* mask = (const float*)d_in[1];
    const float* vf   = (const float*)d_in[2];
    const float* x_r  = (const float*)d_in[3];
    const float* x_w  = (const float*)d_in[4];
    const float* x_k  = (const float*)d_in[5];
    const float* x_v  = (const float*)d_in[6];
    const float* x_a  = (const float*)d_in[7];
    const float* x_g  = (const float*)d_in[8];
    const float* w0   = (const float*)d_in[9];
    const float* w1   = (const float*)d_in[10];
    const float* w2   = (const float*)d_in[11];
    const float* a0   = (const float*)d_in[12];
    const float* a1   = (const float*)d_in[13];
    const float* a2   = (const float*)d_in[14];
    const float* v0   = (const float*)d_in[15];
    const float* v1   = (const float*)d_in[16];
    const float* v2   = (const float*)d_in[17];
    const float* g1   = (const float*)d_in[18];
    const float* g2   = (const float*)d_in[19];
    const float* k_k  = (const float*)d_in[20];
    const float* k_a  = (const float*)d_in[21];
    const float* r_k  = (const float*)d_in[22];
    const float* W_r  = (const float*)d_in[23];
    const float* W_k  = (const float*)d_in[24];
    const float* W_v  = (const float*)d_in[25];
    const float* W_o  = (const float*)d_in[26];
    const float* ln_w = (const float*)d_in[27];
    const float* ln_b = (const float*)d_in[28];

    float* p_r = sym<float>(g_r); float* p_v = sym<float>(g_v);
    float* p_kf = sym<float>(g_k);
    bf16* p_xr = sym<bf16>(g_xr); bf16* p_xk = sym<bf16>(g_xk);
    bf16* p_xv = sym<bf16>(g_xv);
    bf16* p_ygbf = sym<bf16>(g_ygbf);
    bf16* p_Wbf = sym<bf16>(g_Wbf);
    bf16* p_w1t = sym<bf16>(g_w1t);
    bf16* p_w2t = sym<bf16>(g_w2t);

    float* out = (float*)d_out;

    const unsigned EW = (unsigned)((BTC + 255) / 256);
    const unsigned WW = (unsigned)(((size_t)Cn * Cn + 255) / 256);
    const unsigned TW = (unsigned)((KP * Cn + 255) / 256);
    dim3 big(16, 64), mlp1g(1, 64, 4), mlp2g(16, 64, 4);
    const size_t WS = (size_t)Cn * 4096;
    const size_t W1S = (size_t)KP * 4096;
    const size_t W2S = (size_t)Cn * 2 * KP;
    const int SHB = 3 * 128 * 40 * 2 * 2;   // 61440 bytes

    cudaFuncSetAttribute(hgemm<2048, 0>, cudaFuncAttributeMaxDynamicSharedMemorySize, SHB);
    cudaFuncSetAttribute(hgemm<2048, 6>, cudaFuncAttributeMaxDynamicSharedMemorySize, SHB);
    cudaFuncSetAttribute(hgemm<128, 7>,  cudaFuncAttributeMaxDynamicSharedMemorySize, SHB);

    // weight prep
    conv_split<<<WW, 256>>>(W_r, p_Wbf + 0 * WS, Cn);
    conv_split<<<WW, 256>>>(W_k, p_Wbf + 1 * WS, Cn);
    conv_split<<<WW, 256>>>(W_v, p_Wbf + 2 * WS, Cn);
    conv_split<<<WW, 256>>>(W_o, p_Wbf + 3 * WS, Cn);
    tsplit1<<<TW, 256>>>(w1, p_w1t + 0 * W1S, 96);
    tsplit1<<<TW, 256>>>(a1, p_w1t + 1 * W1S, 96);
    tsplit1<<<TW, 256>>>(v1, p_w1t + 2 * W1S, 64);
    tsplit1<<<TW, 256>>>(g1, p_w1t + 3 * W1S, 128);
    tsplit2<<<TW, 256>>>(w2, p_w2t + 0 * W2S, 96);
    tsplit2<<<TW, 256>>>(a2, p_w2t + 1 * W2S, 96);
    tsplit2<<<TW, 256>>>(v2, p_w2t + 2 * W2S, 64);
    tsplit2<<<TW, 256>>>(g2, p_w2t + 3 * W2S, 128);

    // mixing
    mix_split<<<EW, 256>>>(x, mask, x_r, x_w, x_k, x_v, x_a, x_g);

    // batched mlp1 (4 paths)
    hgemm<2048, 6><<<mlp1g, 256, SHB>>>(nullptr, nullptr, nullptr, 128, nullptr, nullptr, nullptr);

    // big projections
    hgemm<2048, 0><<<big, 256, SHB>>>(p_xr, p_Wbf + 0 * WS, p_r,  Cn, nullptr, nullptr, nullptr);
    hgemm<2048, 0><<<big, 256, SHB>>>(p_xk, p_Wbf + 1 * WS, p_kf, Cn, nullptr, nullptr, nullptr);
    hgemm<2048, 0><<<big, 256, SHB>>>(p_xv, p_Wbf + 2 * WS, p_v,  Cn, nullptr, nullptr, nullptr);

    // batched mlp2 (4 paths)
    hgemm<128, 7><<<mlp2g, 256, SHB>>>(nullptr, nullptr, nullptr, Cn, w0, a0, v0);

    // fused v-combine + kk
    kkv_fused<<<BT * Hn / 8, 256>>>(vf, mask, k_k, k_a);

    // scan
    scan_kernel<<<Bn * Hn, 128>>>();

    // post groupnorm
    postln_kernel<<<BT * Hn / 4, 128>>>(r_k, ln_w, ln_b);

    // output projection
    hgemm<2048, 0><<<big, 256, SHB>>>(p_ygbf, p_Wbf + 3 * WS, out, Cn, nullptr, nullptr, nullptr);

    if ((size_t)out_size >= 2 * BTC) {
        cudaMemcpyAsync(out + BTC, vf, BTC * sizeof(float), cudaMemcpyDeviceToDevice, 0);
    }
}

// round 7
// speedup vs baseline: 3.4923x; 1.2959x over previous
#include <cuda_runtime.h>
#include <cuda_bf16.h>
#include <math.h>
#include <stdint.h>

#define Bn 8
#define Tn 1024
#define Cn 2048
#define Hn 32
#define BT (Bn*Tn)                 // 8192
#define BTC ((size_t)BT*Cn)        // 16777216
#define LN_EPS (1e-5f*64.0f)
#define KP 128

typedef __nv_bfloat16 bf16;

// ---------------- scratch ----------------
__device__ float g_r[BTC], g_k[BTC], g_v[BTC], g_wdec[BTC], g_a[BTC], g_vg[BTC];
__device__ float g_g[BTC], g_nkk[BTC], g_ab[BTC], g_knew[BTC], g_y[BTC];
// tiled (pre-swizzled 128x32 tile images) for bulk-TMA GEMMs: per (mb,kt): [hi 4096][lo 4096] bf16
__device__ __align__(128) bf16 g_xrt[(size_t)BT*4096], g_xkt[(size_t)BT*4096], g_xvt[(size_t)BT*4096];
__device__ __align__(128) bf16 g_ygt[(size_t)BT*4096];
// row-layout split-bf16 for mma.sync MLP path
__device__ __align__(128) bf16 g_xw[(size_t)BT*4096], g_xa[(size_t)BT*4096];
__device__ __align__(128) bf16 g_xvr[(size_t)BT*4096], g_xg[(size_t)BT*4096];
// tiled weights: per (nb 0..15, kt 0..63): [hi 4096][lo 4096]
__device__ __align__(128) bf16 g_Wt[4][(size_t)Cn*4096];
__device__ __align__(128) bf16 g_w1t[4][(size_t)KP*4096];
__device__ __align__(128) bf16 g_w2t[4][(size_t)Cn*2*KP];
__device__ __align__(128) bf16 g_hid4[4][(size_t)BT*256];

// ---------------- helpers ----------------
__device__ __forceinline__ void split_store(bf16* dst, size_t hi_idx, size_t lo_off, float v) {
    bf16 hi = __float2bfloat16(v);
    bf16 lo = __float2bfloat16(v - __bfloat162float(hi));
    dst[hi_idx] = hi;
    dst[hi_idx + lo_off] = lo;
}

// tiled index: tile (mb,kt), row r (0..127), col cc (0..31), chunk-XOR swizzle
__device__ __forceinline__ size_t tile_idx(int mb, int kt, int r, int cc) {
    int slot = (cc >> 3) ^ ((r >> 1) & 3);
    return ((size_t)(mb * 64 + kt)) * 8192 + r * 32 + slot * 8 + (cc & 7);
}

__device__ __forceinline__ uint32_t smem_u32(const void* p) {
    return (uint32_t)__cvta_generic_to_shared(p);
}

#define MBAR_INIT(addr, cnt) \
    asm volatile("mbarrier.init.shared.b64 [%0], %1;" :: "r"(addr), "r"(cnt) : "memory")
#define MBAR_ARRIVE(addr) \
    asm volatile("mbarrier.arrive.shared.b64 _, [%0];" :: "r"(addr) : "memory")
#define MBAR_EXPECT_TX(addr, bytes) \
    asm volatile("mbarrier.arrive.expect_tx.shared.b64 _, [%0], %1;" :: "r"(addr), "r"(bytes) : "memory")
#define MBAR_WAIT(addr, parity) do { \
    uint32_t _m = (addr), _p = (parity), _d; \
    asm volatile("{\n\t.reg .pred p;\n\tmbarrier.try_wait.parity.acquire.cta.shared::cta.b64 p, [%1], %2;\n\tselp.b32 %0, 1, 0, p;\n\t}" \
        : "=r"(_d) : "r"(_m), "r"(_p) : "memory"); \
    if (!_d) { \
        asm volatile("{\n\t.reg .pred P1;\n\tWL_%=:\n\tmbarrier.try_wait.parity.acquire.cta.shared::cta.b64 P1, [%0], %1, 0x989680;\n\t@P1 bra.uni WD_%=;\n\tbra.uni WL_%=;\n\tWD_%=:\n\t}" \
            :: "r"(_m), "r"(_p) : "memory"); \
    } \
} while (0)

__device__ __forceinline__ void tma_bulk(uint32_t dst, const void* src, uint32_t bytes, uint32_t mbar) {
    asm volatile("cp.async.bulk.shared::cluster.global.mbarrier::complete_tx::bytes [%0], [%1], %2, [%3];"
                 :: "r"(dst), "l"(src), "r"(bytes), "r"(mbar) : "memory");
}

#define LDSM4(r0, r1, r2, r3, addr) \
    asm volatile("ldmatrix.sync.aligned.m8n8.x4.shared.b16 {%0,%1,%2,%3}, [%4];" \
                 : "=r"(r0), "=r"(r1), "=r"(r2), "=r"(r3) : "r"(addr))

#define MMA16816(c, a, b0, b1) \
    asm volatile("mma.sync.aligned.m16n8k16.row.col.f32.bf16.bf16.f32 " \
                 "{%0,%1,%2,%3}, {%4,%5,%6,%7}, {%8,%9}, {%0,%1,%2,%3};\n" \
                 : "+f"((c)[0]), "+f"((c)[1]), "+f"((c)[2]), "+f"((c)[3]) \
                 : "r"((a)[0]), "r"((a)[1]), "r"((a)[2]), "r"((a)[3]), "r"(b0), "r"(b1))

// ---------------- mixing: tiled (xr,xk,xv) + row (xw,xa,xv,xg) ----------------
__global__ void mix_split(const float* __restrict__ x, const float* __restrict__ mask,
                          const float* __restrict__ mr, const float* __restrict__ mw,
                          const float* __restrict__ mk, const float* __restrict__ mv,
                          const float* __restrict__ ma, const float* __restrict__ mg)
{
    size_t i = (size_t)blockIdx.x * blockDim.x + threadIdx.x;
    if (i >= BTC) return;
    int c = (int)(i % Cn);
    size_t bt = i / Cn;
    int t = (int)(bt % Tn);
    float m  = mask[bt];
    float xm = x[i] * m;
    float xp = 0.f;
    if (t > 0) xp = x[i - Cn] * mask[bt - 1];
    float xx = xp - xm;
    float vr = xm + xx * mr[c], vw = xm + xx * mw[c], vk = xm + xx * mk[c];
    float vv = xm + xx * mv[c], va = xm + xx * ma[c], vg = xm + xx * mg[c];

    int mb = (int)(bt >> 7), r = (int)(bt & 127), kt = c >> 5, cc = c & 31;
    size_t ti = tile_idx(mb, kt, r, cc);
    split_store(g_xrt, ti, 4096, vr);
    split_store(g_xkt, ti, 4096, vk);
    split_store(g_xvt, ti, 4096, vv);

    size_t o = bt * 4096 + c;
    split_store(g_xw,  o, 2048, vw);
    split_store(g_xa,  o, 2048, va);
    split_store(g_xvr, o, 2048, vv);
    split_store(g_xg,  o, 2048, vg);
}

// ---------------- weight conversions ----------------
__global__ void conv_wt(const float* __restrict__ src, bf16* __restrict__ dst)
{
    size_t i = (size_t)blockIdx.x * blockDim.x + threadIdx.x;
    if (i >= (size_t)Cn * Cn) return;
    int n = (int)(i / Cn), k = (int)(i % Cn);
    split_store(dst, tile_idx(n >> 7, k >> 5, n & 127, k & 31), 4096, src[i]);
}

__global__ void tsplit1(const float* __restrict__ in, bf16* __restrict__ out, int nd)
{
    int i = blockIdx.x * blockDim.x + threadIdx.x;
    if (i >= KP * Cn) return;
    int n = i / Cn, k = i % Cn;
    float v = (n < nd) ? in[(size_t)k * nd + n] : 0.f;
    split_store(out, (size_t)n * 4096 + k, 2048, v);
}

__global__ void tsplit2(const float* __restrict__ in, bf16* __restrict__ out, int nd)
{
    int i = blockIdx.x * blockDim.x + threadIdx.x;
    if (i >= Cn * KP) return;
    int n = i / KP, k = i % KP;
    float v = (k < nd) ? in[(size_t)k * Cn + n] : 0.f;
    split_store(out, (size_t)n * (2 * KP) + k, KP, v);
}

// ---------------- bulk-TMA + mma.sync split-bf16 GEMM: C[8192,2048] = A @ B^T ----------------
// stage smem: [Ah 8K][Al 8K][Bh 8K][Bl 8K] = 32KB; 3 stages; barriers at base.
__global__ __launch_bounds__(256, 2)
void bgemm(const bf16* __restrict__ Aop, const bf16* __restrict__ Bop,
           float* __restrict__ Cop, int multi)
{
    extern __shared__ __align__(1024) char smem[];
    const uint32_t sb = smem_u32(smem);
    const int tid = threadIdx.x, w = tid >> 5, lane = tid & 31;
    const int bn = blockIdx.x, bm = blockIdx.y, z = blockIdx.z;
    const int wm = (w & 3) * 32, wn = (w >> 2) * 64;

    const bf16* A = Aop; const bf16* Bw = Bop; float* C = Cop;
    if (multi) {
        A = (z == 0) ? g_xrt : (z == 1) ? g_xkt : g_xvt;
        Bw = g_Wt[z];
        C = (z == 0) ? g_r : (z == 1) ? g_k : g_v;
    }

    const uint32_t FULL = sb;          // 3 x 8B
    const uint32_t EMPTY = sb + 64;    // 3 x 8B
    const uint32_t ST = sb + 1024;

    if (tid == 0) {
#pragma unroll
        for (int s = 0; s < 3; s++) { MBAR_INIT(FULL + 8 * s, 1); MBAR_INIT(EMPTY + 8 * s, 8); }
    }
    __syncthreads();

    if (tid == 0) {
#pragma unroll
        for (int t = 0; t < 2; t++) {
            MBAR_EXPECT_TX(FULL + 8 * t, 32768u);
            tma_bulk(ST + t * 32768,         A  + ((size_t)(bm * 64 + t)) * 8192, 16384u, FULL + 8 * t);
            tma_bulk(ST + t * 32768 + 16384, Bw + ((size_t)(bn * 64 + t)) * 8192, 16384u, FULL + 8 * t);
        }
    }

    float acc[2][8][4];
#pragma unroll
    for (int mi = 0; mi < 2; mi++)
#pragma unroll
        for (int ni = 0; ni < 8; ni++)
#pragma unroll
            for (int q = 0; q < 4; q++) acc[mi][ni][q] = 0.f;

    for (int t = 0; t < 64; t++) {
        int s = t % 3;
        if (tid == 0 && t + 2 < 64) {
            int tp = t + 2, sp = tp % 3, up = tp / 3;
            if (up >= 1) MBAR_WAIT(EMPTY + 8 * sp, (up - 1) & 1);
            MBAR_EXPECT_TX(FULL + 8 * sp, 32768u);
            tma_bulk(ST + sp * 32768,         A  + ((size_t)(bm * 64 + tp)) * 8192, 16384u, FULL + 8 * sp);
            tma_bulk(ST + sp * 32768 + 16384, Bw + ((size_t)(bn * 64 + tp)) * 8192, 16384u, FULL + 8 * sp);
        }
        MBAR_WAIT(FULL + 8 * s, (t / 3) & 1);
        const uint32_t st = ST + s * 32768;

#pragma unroll
        for (int kk = 0; kk < 32; kk += 16) {
            // A fragments (hi and lo)
            uint32_t ah[2][4], al[2][4];
#pragma unroll
            for (int mi = 0; mi < 2; mi++) {
                int rr = wm + mi * 16 + (lane & 15);
                int c8 = (kk >> 3) + (lane >> 4);
                int slot = c8 ^ ((rr >> 1) & 3);
                uint32_t ad = st + (uint32_t)(rr * 64 + slot * 16);
                LDSM4(ah[mi][0], ah[mi][1], ah[mi][2], ah[mi][3], ad);
                LDSM4(al[mi][0], al[mi][1], al[mi][2], al[mi][3], ad + 8192);
            }
#pragma unroll
            for (int n2 = 0; n2 < 4; n2++) {
                int rb = wn + n2 * 16 + (lane & 7) + ((lane & 16) ? 8 : 0);
                int c8 = (kk >> 3) + ((lane & 8) ? 1 : 0);
                int slot = c8 ^ ((rb >> 1) & 3);
                uint32_t bd = st + 16384 + (uint32_t)(rb * 64 + slot * 16);
                uint32_t bh[4], bl[4];
                LDSM4(bh[0], bh[1], bh[2], bh[3], bd);
                LDSM4(bl[0], bl[1], bl[2], bl[3], bd + 8192);
#pragma unroll
                for (int mi = 0; mi < 2; mi++) {
                    MMA16816(acc[mi][2 * n2],     ah[mi], bh[0], bh[1]);
                    MMA16816(acc[mi][2 * n2 + 1], ah[mi], bh[2], bh[3]);
                    MMA16816(acc[mi][2 * n2],     al[mi], bh[0], bh[1]);
                    MMA16816(acc[mi][2 * n2 + 1], al[mi], bh[2], bh[3]);
                    MMA16816(acc[mi][2 * n2],     ah[mi], bl[0], bl[1]);
                    MMA16816(acc[mi][2 * n2 + 1], ah[mi], bl[2], bl[3]);
                }
            }
        }
        if (lane == 0) MBAR_ARRIVE(EMPTY + 8 * s);
    }

#pragma unroll
    for (int mi = 0; mi < 2; mi++)
#pragma unroll
        for (int ni = 0; ni < 8; ni++) {
            int row = bm * 128 + wm + mi * 16 + (lane >> 2);
            int col = bn * 128 + wn + ni * 8 + (lane & 3) * 2;
            float* c = acc[mi][ni];
            C[(size_t)row * Cn + col]           = c[0];
            C[(size_t)row * Cn + col + 1]       = c[1];
            C[(size_t)(row + 8) * Cn + col]     = c[2];
            C[(size_t)(row + 8) * Cn + col + 1] = c[3];
        }
}

// ---------------- mma.sync GEMM for MLPs ----------------
template<int KA, int MODE>
__global__ __launch_bounds__(256, 2)
void hgemm(float* __restrict__ Cf, int ncols,
           const float* __restrict__ b0, const float* __restrict__ b1,
           const float* __restrict__ b2)
{
    constexpr int TPS = KA / 32;
    constexpr int KT  = 3 * TPS;
    constexpr int SSZ = 128 * 40;
    extern __shared__ bf16 sh[];
    bf16* As = sh;
    bf16* Bs = sh + 3 * SSZ;

    const int tid = threadIdx.x;
    const int z = blockIdx.z;
    const int bm = blockIdx.y * 128, bn = blockIdx.x * 128;
    const int w = tid >> 5, lane = tid & 31;
    const int wm = (w & 3) * 32, wn = (w >> 2) * 64;

    const bf16* A;
    const bf16* Bw;
    if (MODE == 6) {
        A = (z == 0) ? g_xw : (z == 1) ? g_xa : (z == 2) ? g_xvr : g_xg;
        Bw = g_w1t[z];
    } else {
        A = g_hid4[z];
        Bw = g_w2t[z];
    }

    float acc[2][8][4];
#pragma unroll
    for (int mi = 0; mi < 2; mi++)
#pragma unroll
        for (int ni = 0; ni < 8; ni++)
#pragma unroll
            for (int q = 0; q < 4; q++) acc[mi][ni][q] = 0.f;

    auto loadtile = [&](int stage, int t) {
        int seg = t / TPS, kk = (t % TPS) * 32;
        int aoff = (seg == 1 ? KA : 0) + kk;
        int boff = (seg == 2 ? KA : 0) + kk;
        bf16* as = As + stage * SSZ;
        bf16* bs = Bs + stage * SSZ;
#pragma unroll
        for (int c = 0; c < 2; c++) {
            int ch = tid + c * 256;
            int row = ch >> 2, col = ch & 3;
            unsigned sa = (unsigned)__cvta_generic_to_shared(&as[row * 40 + col * 8]);
            const void* ga = &A[(size_t)(bm + row) * (2 * KA) + aoff + col * 8];
            asm volatile("cp.async.cg.shared.global [%0], [%1], 16;\n" :: "r"(sa), "l"(ga));
            unsigned sb2 = (unsigned)__cvta_generic_to_shared(&bs[row * 40 + col * 8]);
            const void* gb = &Bw[(size_t)(bn + row) * (2 * KA) + boff + col * 8];
            asm volatile("cp.async.cg.shared.global [%0], [%1], 16;\n" :: "r"(sb2), "l"(gb));
        }
        asm volatile("cp.async.commit_group;\n" ::: "memory");
    };

    loadtile(0, 0);
    loadtile(1, 1);

    const int arow = wm + (lane & 15);
    const int acolo = (lane >> 4) << 3;
    const int brow = (lane & 7) + ((lane & 16) ? 8 : 0);
    const int bcolo = (lane & 8) ? 8 : 0;

    for (int t = 0; t < KT; t++) {
        if (t + 1 < KT) {
            asm volatile("cp.async.wait_group 1;\n" ::: "memory");
        } else {
            asm volatile("cp.async.wait_group 0;\n" ::: "memory");
        }
        __syncthreads();
        if (t + 2 < KT) loadtile((t + 2) % 3, t + 2);

        const bf16* as = As + (t % 3) * SSZ;
        const bf16* bs = Bs + (t % 3) * SSZ;
        unsigned abase = (unsigned)__cvta_generic_to_shared(as);
        unsigned bbase = (unsigned)__cvta_generic_to_shared(bs);

#pragma unroll
        for (int kk = 0; kk < 32; kk += 16) {
            uint32_t af[2][4];
#pragma unroll
            for (int mi = 0; mi < 2; mi++) {
                unsigned aaddr = abase + (unsigned)(((arow + mi * 16) * 40 + kk + acolo) * 2);
                LDSM4(af[mi][0], af[mi][1], af[mi][2], af[mi][3], aaddr);
            }
            uint32_t bq[4][4];
#pragma unroll
            for (int n2 = 0; n2 < 4; n2++) {
                unsigned baddr = bbase + (unsigned)(((wn + n2 * 16 + brow) * 40 + kk + bcolo) * 2);
                LDSM4(bq[n2][0], bq[n2][1], bq[n2][2], bq[n2][3], baddr);
            }
#pragma unroll
            for (int n2 = 0; n2 < 4; n2++) {
#pragma unroll
                for (int mi = 0; mi < 2; mi++) {
                    MMA16816(acc[mi][2 * n2],     af[mi], bq[n2][0], bq[n2][1]);
                    MMA16816(acc[mi][2 * n2 + 1], af[mi], bq[n2][2], bq[n2][3]);
                }
            }
        }
        __syncthreads();
    }

#pragma unroll
    for (int mi = 0; mi < 2; mi++)
#pragma unroll
        for (int ni = 0; ni < 8; ni++) {
            int row = bm + wm + mi * 16 + (lane >> 2);
            int col = bn + wn + ni * 8 + (lane & 3) * 2;
            float* c = acc[mi][ni];
            if (MODE == 6) {
                bf16* hid = g_hid4[z];
                auto act = [&](float v) -> float {
                    if (z == 0) return tanhf(v);
                    if (z == 3) return 1.f / (1.f + expf(-v));
                    return v;
                };
                split_store(hid, (size_t)row * 256 + col,           KP, act(c[0]));
                split_store(hid, (size_t)row * 256 + col + 1,       KP, act(c[1]));
                split_store(hid, (size_t)(row + 8) * 256 + col,     KP, act(c[2]));
                split_store(hid, (size_t)(row + 8) * 256 + col + 1, KP, act(c[3]));
            } else {
                float* dst = (z == 0) ? g_wdec : (z == 1) ? g_a : (z == 2) ? g_vg : g_g;
                auto epi = [&](float v, int n) -> float {
                    if (z == 0) return expf(-0.60653066f / (1.f + expf(-(b0[n] + v))));
                    if (z == 1) return 1.f / (1.f + expf(-(b1[n] + v)));
                    if (z == 2) return 1.f / (1.f + expf(-(b2[n] + v)));
                    return v;
                };
                dst[(size_t)row * Cn + col]           = epi(c[0], col);
                dst[(size_t)row * Cn + col + 1]       = epi(c[1], col + 1);
                dst[(size_t)(row + 8) * Cn + col]     = epi(c[2], col);
                dst[(size_t)(row + 8) * Cn + col + 1] = epi(c[3], col + 1);
            }
        }
}

// ---------------- fused: v-combine + kk-normalize + k-update ----------------
__global__ __launch_bounds__(256)
void kkv_fused(const float* __restrict__ vf, const float* __restrict__ mask,
               const float* __restrict__ kkw, const float* __restrict__ kaw)
{
    const int warp = threadIdx.x >> 5, lane = threadIdx.x & 31;
    const int gid = blockIdx.x * 8 + warp;
    const int h = gid & (Hn - 1);
    const int bt = gid >> 5;
    size_t base = (size_t)gid * 64;
    int c0 = h * 64 + lane, c1 = c0 + 32;
    float m = mask[bt];

    float v0v = g_v[base + lane], v1v = g_v[base + lane + 32];
    float gt0 = g_vg[base + lane], gt1 = g_vg[base + lane + 32];
    v0v = (v0v + (vf[base + lane] - v0v) * gt0) * m;
    v1v = (v1v + (vf[base + lane + 32] - v1v) * gt1) * m;
    g_v[base + lane] = v0v;
    g_v[base + lane + 32] = v1v;

    float k0v = g_k[base + lane], k1v = g_k[base + lane + 32];
    float kk0 = k0v * kkw[c0], kk1 = k1v * kkw[c1];
    float ss = kk0 * kk0 + kk1 * kk1;
#pragma unroll
    for (int off = 16; off > 0; off >>= 1) ss += __shfl_xor_sync(0xffffffffu, ss, off);
    float inv = 1.f / fmaxf(sqrtf(ss), 1e-12f);
    float a0v = g_a[base + lane], a1v = g_a[base + lane + 32];
    g_nkk[base + lane]      = -kk0 * inv;
    g_nkk[base + lane + 32] = -kk1 * inv;
    g_ab[base + lane]       = kk0 * inv * a0v;
    g_ab[base + lane + 32]  = kk1 * inv * a1v;
    g_knew[base + lane]      = k0v * (1.f + (a0v - 1.f) * kaw[c0]);
    g_knew[base + lane + 32] = k1v * (1.f + (a1v - 1.f) * kaw[c1]);
}

// ---------------- RWKV-7 scan: 128 threads, 2 per state row ----------------
__global__ __launch_bounds__(128)
void scan_kernel()
{
    const int bh = blockIdx.x;
    const int b = bh >> 5, h = bh & 31;
    const int tid = threadIdx.x;
    const int j = tid >> 1, half = tid & 1;
    size_t base = (size_t)b * Tn * Cn + h * 64;

    float S[32];
#pragma unroll
    for (int i = 0; i < 32; i++) S[i] = 0.f;

    __shared__ float sm[2][384];

    const float* gsrc0;
    const float* gsrc1;
    const float* gsrc2;
    {
        const float* tbl[6] = {g_r, g_wdec, g_knew, g_v, g_nkk, g_ab};
        int l0 = tid, l1 = tid + 128, l2 = tid + 256;
        gsrc0 = tbl[l0 >> 6] + base + (l0 & 63);
        gsrc1 = tbl[l1 >> 6] + base + (l1 & 63);
        gsrc2 = tbl[l2 >> 6] + base + (l2 & 63);
    }
    float f0 = *gsrc0, f1 = *gsrc1, f2 = *gsrc2;

    for (int t = 0; t < Tn; t++) {
        float* sb = sm[t & 1];
        sb[tid] = f0; sb[tid + 128] = f1; sb[tid + 256] = f2;
        __syncthreads();

        if (t + 1 < Tn) {
            gsrc0 += Cn; gsrc1 += Cn; gsrc2 += Cn;
            f0 = *gsrc0; f1 = *gsrc1; f2 = *gsrc2;
        }

        const float* rv = sb + half * 32;
        const float* wv = sb + 64 + half * 32;
        const float* kv = sb + 128 + half * 32;
        const float* av = sb + 256 + half * 32;
        const float* bv = sb + 320 + half * 32;

        float sa = 0.f;
#pragma unroll
        for (int ii = 0; ii < 32; ii++) sa = fmaf(S[ii], av[ii], sa);
        sa += __shfl_xor_sync(0xffffffffu, sa, 1);

        float vj = sb[192 + j];
        float y = 0.f;
#pragma unroll
        for (int ii = 0; ii < 32; ii++) {
            float s = fmaf(S[ii], wv[ii], fmaf(sa, bv[ii], vj * kv[ii]));
            S[ii] = s;
            y = fmaf(s, rv[ii], y);
        }
        y += __shfl_xor_sync(0xffffffffu, y, 1);
        if (!half) g_y[base + (size_t)t * Cn + j] = y;
    }
}

// ---------------- groupnorm + rk bonus + gate -> tiled split bf16 ----------------
__global__ __launch_bounds__(128)
void postln_kernel(const float* __restrict__ rkw, const float* __restrict__ lnw,
                   const float* __restrict__ lnb)
{
    const int warp = threadIdx.x >> 5, lane = threadIdx.x & 31;
    const int gid = blockIdx.x * 4 + warp;
    const int h = gid & (Hn - 1);
    const int bt = gid >> 5;
    size_t base = (size_t)gid * 64;
    int c0 = h * 64 + lane, c1 = c0 + 32;

    float y0 = g_y[base + lane], y1 = g_y[base + lane + 32];
    float s = y0 + y1;
#pragma unroll
    for (int off = 16; off > 0; off >>= 1) s += __shfl_xor_sync(0xffffffffu, s, off);
    float mu = s * (1.f / 64.f);
    float d0 = y0 - mu, d1 = y1 - mu;
    float vs = d0 * d0 + d1 * d1;
#pragma unroll
    for (int off = 16; off > 0; off >>= 1) vs += __shfl_xor_sync(0xffffffffu, vs, off);
    float inv = rsqrtf(vs * (1.f / 64.f) + LN_EPS);

    float rk = g_r[base + lane] * g_knew[base + lane] * rkw[c0]
             + g_r[base + lane + 32] * g_knew[base + lane + 32] * rkw[c1];
#pragma unroll
    for (int off = 16; off > 0; off >>= 1) rk += __shfl_xor_sync(0xffffffffu, rk, off);

    float yn0 = d0 * inv * lnw[c0] + lnb[c0];
    float yn1 = d1 * inv * lnw[c1] + lnb[c1];
    float o0 = (yn0 + rk * g_v[base + lane])      * g_g[base + lane];
    float o1 = (yn1 + rk * g_v[base + lane + 32]) * g_g[base + lane + 32];

    int mb = bt >> 7, r = bt & 127;
    split_store(g_ygt, tile_idx(mb, c0 >> 5, r, c0 & 31), 4096, o0);
    split_store(g_ygt, tile_idx(mb, c1 >> 5, r, c1 & 31), 4096, o1);
}

// ---------------- host ----------------
template<typename T> static T* sym(const void* s) { void* p = nullptr; cudaGetSymbolAddress(&p, s); return (T*)p; }

extern "C" void kernel_launch(void* const* d_in, const int* in_sizes, int n_in,
                              void* d_out, int out_size)
{
    const float* x    = (const float*)d_in[0];
    const float* mask = (const float*)d_in[1];
    const float* vf   = (const float*)d_in[2];
    const float* x_r  = (const float*)d_in[3];
    const float* x_w  = (const float*)d_in[4];
    const float* x_k  = (const float*)d_in[5];
    const float* x_v  = (const float*)d_in[6];
    const float* x_a  = (const float*)d_in[7];
    const float* x_g  = (const float*)d_in[8];
    const float* w0   = (const float*)d_in[9];
    const float* w1   = (const float*)d_in[10];
    const float* w2   = (const float*)d_in[11];
    const float* a0   = (const float*)d_in[12];
    const float* a1   = (const float*)d_in[13];
    const float* a2   = (const float*)d_in[14];
    const float* v0   = (const float*)d_in[15];
    const float* v1   = (const float*)d_in[16];
    const float* v2   = (const float*)d_in[17];
    const float* g1   = (const float*)d_in[18];
    const float* g2   = (const float*)d_in[19];
    const float* k_k  = (const float*)d_in[20];
    const float* k_a  = (const float*)d_in[21];
    const float* r_k  = (const float*)d_in[22];
    const float* W_r  = (const float*)d_in[23];
    const float* W_k  = (const float*)d_in[24];
    const float* W_v  = (const float*)d_in[25];
    const float* W_o  = (const float*)d_in[26];
    const float* ln_w = (const float*)d_in[27];
    const float* ln_b = (const float*)d_in[28];

    bf16* p_Wt  = sym<bf16>(g_Wt);
    bf16* p_w1t = sym<bf16>(g_w1t);
    bf16* p_w2t = sym<bf16>(g_w2t);
    bf16* p_ygt = sym<bf16>(g_ygt);

    float* out = (float*)d_out;

    const unsigned EW = (unsigned)((BTC + 255) / 256);
    const unsigned WW = (unsigned)(((size_t)Cn * Cn + 255) / 256);
    const unsigned TW = (unsigned)((KP * Cn + 255) / 256);
    const size_t WS = (size_t)Cn * 4096;
    const size_t W1S = (size_t)KP * 4096;
    const size_t W2S = (size_t)Cn * 2 * KP;
    const int SHB = 3 * 128 * 40 * 2 * 2;       // mma.sync smem (61440)
    const int BSH = 1024 + 3 * 32768;           // bgemm smem (99328)

    cudaFuncSetAttribute(hgemm<2048, 6>, cudaFuncAttributeMaxDynamicSharedMemorySize, SHB);
    cudaFuncSetAttribute(hgemm<128, 7>,  cudaFuncAttributeMaxDynamicSharedMemorySize, SHB);
    cudaFuncSetAttribute(bgemm, cudaFuncAttributeMaxDynamicSharedMemorySize, BSH);

    // weight prep
    conv_wt<<<WW, 256>>>(W_r, p_Wt + 0 * WS);
    conv_wt<<<WW, 256>>>(W_k, p_Wt + 1 * WS);
    conv_wt<<<WW, 256>>>(W_v, p_Wt + 2 * WS);
    conv_wt<<<WW, 256>>>(W_o, p_Wt + 3 * WS);
    tsplit1<<<TW, 256>>>(w1, p_w1t + 0 * W1S, 96);
    tsplit1<<<TW, 256>>>(a1, p_w1t + 1 * W1S, 96);
    tsplit1<<<TW, 256>>>(v1, p_w1t + 2 * W1S, 64);
    tsplit1<<<TW, 256>>>(g1, p_w1t + 3 * W1S, 128);
    tsplit2<<<TW, 256>>>(w2, p_w2t + 0 * W2S, 96);
    tsplit2<<<TW, 256>>>(a2, p_w2t + 1 * W2S, 96);
    tsplit2<<<TW, 256>>>(v2, p_w2t + 2 * W2S, 64);
    tsplit2<<<TW, 256>>>(g2, p_w2t + 3 * W2S, 128);

    // mixing
    mix_split<<<EW, 256>>>(x, mask, x_r, x_w, x_k, x_v, x_a, x_g);

    // batched mlp1 (4 paths) on mma.sync
    hgemm<2048, 6><<<dim3(1, 64, 4), 256, SHB>>>(nullptr, 128, nullptr, nullptr, nullptr);

    // big projections r/k/v on bulk-TMA mma.sync
    bgemm<<<dim3(16, 64, 3), 256, BSH>>>(nullptr, nullptr, nullptr, 1);

    // batched mlp2 (4 paths)
    hgemm<128, 7><<<dim3(16, 64, 4), 256, SHB>>>(nullptr, Cn, w0, a0, v0);

    // fused v-combine + kk
    kkv_fused<<<BT * Hn / 8, 256>>>(vf, mask, k_k, k_a);

    // scan
    scan_kernel<<<Bn * Hn, 128>>>();

    // post groupnorm -> tiled
    postln_kernel<<<BT * Hn / 4, 128>>>(r_k, ln_w, ln_b);

    // output projection
    bgemm<<<dim3(16, 64, 1), 256, BSH>>>(p_ygt, p_Wt + 3 * WS, out, 0);

    if ((size_t)out_size >= 2 * BTC) {
        cudaMemcpyAsync(out + BTC, vf, BTC * sizeof(float), cudaMemcpyDeviceToDevice, 0);
    }
}

// round 9
// speedup vs baseline: 3.8113x; 1.0913x over previous
#include <cuda_runtime.h>
#include <cuda_bf16.h>
#include <cuda_fp16.h>
#include <math.h>
#include <stdint.h>

#define Bn 8
#define Tn 1024
#define Cn 2048
#define Hn 32
#define BT (Bn*Tn)                 // 8192
#define BTC ((size_t)BT*Cn)        // 16777216
#define LN_EPS (1e-5f*64.0f)
#define KP 128

typedef __nv_bfloat16 bf16;

// ---------------- scratch ----------------
__device__ float g_r[BTC], g_k[BTC], g_v[BTC], g_wdec[BTC], g_a[BTC], g_vg[BTC];
__device__ float g_g[BTC], g_nkk[BTC], g_ab[BTC], g_knew[BTC], g_y[BTC];
// bf16-split tiled (128x32 tile images [hi 4096][lo 4096], chunk-XOR swizzle) for r/k/v GEMMs
__device__ __align__(128) bf16 g_xrt[(size_t)BT*4096], g_xkt[(size_t)BT*4096], g_xvt[(size_t)BT*4096];
__device__ __align__(128) bf16 g_Wt[3][(size_t)Cn*4096];
// fp16 tiled (128x32 tile images, 4096 halfs/tile) for out projection
__device__ __align__(128) __half g_ygt[(size_t)BT*2048];
__device__ __align__(128) __half g_Wo16[(size_t)Cn*2048];
// row-layout split-bf16 for mma.sync MLP path
__device__ __align__(128) bf16 g_xw[(size_t)BT*4096], g_xa[(size_t)BT*4096];
__device__ __align__(128) bf16 g_xvr[(size_t)BT*4096], g_xg[(size_t)BT*4096];
__device__ __align__(128) bf16 g_w1t[4][(size_t)KP*4096];
__device__ __align__(128) bf16 g_w2t[4][(size_t)Cn*2*KP];
__device__ __align__(128) bf16 g_hid4[4][(size_t)BT*256];

// ---------------- helpers ----------------
__device__ __forceinline__ void split_store(bf16* dst, size_t hi_idx, size_t lo_off, float v) {
    bf16 hi = __float2bfloat16(v);
    bf16 lo = __float2bfloat16(v - __bfloat162float(hi));
    dst[hi_idx] = hi;
    dst[hi_idx + lo_off] = lo;
}

// bf16-split tile index: tile (mb,kt) = 8192 bf16 ([hi 4096][lo 4096]); lo_off = 4096
__device__ __forceinline__ size_t tile_idx8(int mb, int kt, int r, int cc) {
    int slot = (cc >> 3) ^ ((r >> 1) & 3);
    return ((size_t)(mb * 64 + kt)) * 8192 + r * 32 + slot * 8 + (cc & 7);
}
// fp16 tile index: tile (mb,kt) = 4096 halfs
__device__ __forceinline__ size_t tile_idx4(int mb, int kt, int r, int cc) {
    int slot = (cc >> 3) ^ ((r >> 1) & 3);
    return ((size_t)(mb * 64 + kt)) * 4096 + r * 32 + slot * 8 + (cc & 7);
}

__device__ __forceinline__ uint32_t smem_u32(const void* p) {
    return (uint32_t)__cvta_generic_to_shared(p);
}

#define MBAR_INIT(addr, cnt) \
    asm volatile("mbarrier.init.shared.b64 [%0], %1;" :: "r"(addr), "r"(cnt) : "memory")
#define MBAR_ARRIVE(addr) \
    asm volatile("mbarrier.arrive.shared.b64 _, [%0];" :: "r"(addr) : "memory")
#define MBAR_EXPECT_TX(addr, bytes) \
    asm volatile("mbarrier.arrive.expect_tx.shared.b64 _, [%0], %1;" :: "r"(addr), "r"(bytes) : "memory")
#define MBAR_WAIT(addr, parity) do { \
    uint32_t _m = (addr), _p = (parity), _d; \
    asm volatile("{\n\t.reg .pred p;\n\tmbarrier.try_wait.parity.acquire.cta.shared::cta.b64 p, [%1], %2;\n\tselp.b32 %0, 1, 0, p;\n\t}" \
        : "=r"(_d) : "r"(_m), "r"(_p) : "memory"); \
    if (!_d) { \
        asm volatile("{\n\t.reg .pred P1;\n\tWL_%=:\n\tmbarrier.try_wait.parity.acquire.cta.shared::cta.b64 P1, [%0], %1, 0x989680;\n\t@P1 bra.uni WD_%=;\n\tbra.uni WL_%=;\n\tWD_%=:\n\t}" \
            :: "r"(_m), "r"(_p) : "memory"); \
    } \
} while (0)

__device__ __forceinline__ void tma_bulk(uint32_t dst, const void* src, uint32_t bytes, uint32_t mbar) {
    asm volatile("cp.async.bulk.shared::cluster.global.mbarrier::complete_tx::bytes [%0], [%1], %2, [%3];"
                 :: "r"(dst), "l"(src), "r"(bytes), "r"(mbar) : "memory");
}

#define LDSM4(r0, r1, r2, r3, addr) \
    asm volatile("ldmatrix.sync.aligned.m8n8.x4.shared.b16 {%0,%1,%2,%3}, [%4];" \
                 : "=r"(r0), "=r"(r1), "=r"(r2), "=r"(r3) : "r"(addr))

#define MMA_BF(c, a, b0, b1) \
    asm volatile("mma.sync.aligned.m16n8k16.row.col.f32.bf16.bf16.f32 " \
                 "{%0,%1,%2,%3}, {%4,%5,%6,%7}, {%8,%9}, {%0,%1,%2,%3};\n" \
                 : "+f"((c)[0]), "+f"((c)[1]), "+f"((c)[2]), "+f"((c)[3]) \
                 : "r"((a)[0]), "r"((a)[1]), "r"((a)[2]), "r"((a)[3]), "r"(b0), "r"(b1))

#define MMA_FP(c, a, b0, b1) \
    asm volatile("mma.sync.aligned.m16n8k16.row.col.f32.f16.f16.f32 " \
                 "{%0,%1,%2,%3}, {%4,%5,%6,%7}, {%8,%9}, {%0,%1,%2,%3};\n" \
                 : "+f"((c)[0]), "+f"((c)[1]), "+f"((c)[2]), "+f"((c)[3]) \
                 : "r"((a)[0]), "r"((a)[1]), "r"((a)[2]), "r"((a)[3]), "r"(b0), "r"(b1))

// ---------------- mixing: bf16-split tiled (xr,xk,xv) + bf16 row (xw,xa,xv,xg) ----------------
__global__ void mix_split(const float* __restrict__ x, const float* __restrict__ mask,
                          const float* __restrict__ mr, const float* __restrict__ mw,
                          const float* __restrict__ mk, const float* __restrict__ mv,
                          const float* __restrict__ ma, const float* __restrict__ mg)
{
    size_t i = (size_t)blockIdx.x * blockDim.x + threadIdx.x;
    if (i >= BTC) return;
    int c = (int)(i % Cn);
    size_t bt = i / Cn;
    int t = (int)(bt % Tn);
    float m  = mask[bt];
    float xm = x[i] * m;
    float xp = 0.f;
    if (t > 0) xp = x[i - Cn] * mask[bt - 1];
    float xx = xp - xm;
    float vr = xm + xx * mr[c], vw = xm + xx * mw[c], vk = xm + xx * mk[c];
    float vv = xm + xx * mv[c], va = xm + xx * ma[c], vg = xm + xx * mg[c];

    int mb = (int)(bt >> 7), r = (int)(bt & 127), kt = c >> 5, cc = c & 31;
    size_t ti = tile_idx8(mb, kt, r, cc);
    split_store(g_xrt, ti, 4096, vr);
    split_store(g_xkt, ti, 4096, vk);
    split_store(g_xvt, ti, 4096, vv);

    size_t o = bt * 4096 + c;
    split_store(g_xw,  o, 2048, vw);
    split_store(g_xa,  o, 2048, va);
    split_store(g_xvr, o, 2048, vv);
    split_store(g_xg,  o, 2048, vg);
}

// ---------------- weight conversions (batched over z) ----------------
__global__ void conv_wt4(const float* __restrict__ Wr, const float* __restrict__ Wk,
                         const float* __restrict__ Wv, const float* __restrict__ Wo)
{
    size_t i = (size_t)blockIdx.x * blockDim.x + threadIdx.x;
    if (i >= (size_t)Cn * Cn) return;
    int z = blockIdx.y;
    int n = (int)(i / Cn), k = (int)(i % Cn);
    if (z < 3) {
        const float* src = (z == 0) ? Wr : (z == 1) ? Wk : Wv;
        split_store(g_Wt[z], tile_idx8(n >> 7, k >> 5, n & 127, k & 31), 4096, src[i]);
    } else {
        g_Wo16[tile_idx4(n >> 7, k >> 5, n & 127, k & 31)] = __float2half(Wo[i]);
    }
}

__global__ void tsplit1_4(const float* __restrict__ w1, const float* __restrict__ a1,
                          const float* __restrict__ v1, const float* __restrict__ g1)
{
    int i = blockIdx.x * blockDim.x + threadIdx.x;
    if (i >= KP * Cn) return;
    int z = blockIdx.y;
    const float* in = (z == 0) ? w1 : (z == 1) ? a1 : (z == 2) ? v1 : g1;
    int nd = (z == 2) ? 64 : (z == 3) ? 128 : 96;
    int n = i / Cn, k = i % Cn;
    float v = (n < nd) ? in[(size_t)k * nd + n] : 0.f;
    split_store(g_w1t[z], (size_t)n * 4096 + k, 2048, v);
}

__global__ void tsplit2_4(const float* __restrict__ w2, const float* __restrict__ a2,
                          const float* __restrict__ v2, const float* __restrict__ g2)
{
    int i = blockIdx.x * blockDim.x + threadIdx.x;
    if (i >= Cn * KP) return;
    int z = blockIdx.y;
    const float* in = (z == 0) ? w2 : (z == 1) ? a2 : (z == 2) ? v2 : g2;
    int nd = (z == 2) ? 64 : (z == 3) ? 128 : 96;
    int n = i / KP, k = i % KP;
    float v = (k < nd) ? in[(size_t)k * Cn + n] : 0.f;
    split_store(g_w2t[z], (size_t)n * (2 * KP) + k, KP, v);
}

// ---------------- bulk-TMA bf16 3-term GEMM (r/k/v): 32KB/stage, 3 stages ----------------
__global__ __launch_bounds__(256, 2)
void bgemm3()
{
    extern __shared__ __align__(1024) char smem[];
    const uint32_t sb = smem_u32(smem);
    const int tid = threadIdx.x, w = tid >> 5, lane = tid & 31;
    const int bn = blockIdx.x, bm = blockIdx.y, z = blockIdx.z;
    const int wm = (w & 3) * 32, wn = (w >> 2) * 64;

    const bf16* A = (z == 0) ? g_xrt : (z == 1) ? g_xkt : g_xvt;
    const bf16* Bw = g_Wt[z];
    float* C = (z == 0) ? g_r : (z == 1) ? g_k : g_v;

    const uint32_t FULL = sb;
    const uint32_t EMPTY = sb + 64;
    const uint32_t ST = sb + 1024;

    if (tid == 0) {
#pragma unroll
        for (int s = 0; s < 3; s++) { MBAR_INIT(FULL + 8 * s, 1); MBAR_INIT(EMPTY + 8 * s, 8); }
    }
    __syncthreads();

    if (tid == 0) {
#pragma unroll
        for (int t = 0; t < 2; t++) {
            MBAR_EXPECT_TX(FULL + 8 * t, 32768u);
            tma_bulk(ST + t * 32768,         A  + ((size_t)(bm * 64 + t)) * 8192, 16384u, FULL + 8 * t);
            tma_bulk(ST + t * 32768 + 16384, Bw + ((size_t)(bn * 64 + t)) * 8192, 16384u, FULL + 8 * t);
        }
    }

    float acc[2][8][4];
#pragma unroll
    for (int mi = 0; mi < 2; mi++)
#pragma unroll
        for (int ni = 0; ni < 8; ni++)
#pragma unroll
            for (int q = 0; q < 4; q++) acc[mi][ni][q] = 0.f;

    for (int t = 0; t < 64; t++) {
        int s = t % 3;
        if (tid == 0 && t + 2 < 64) {
            int tp = t + 2, sp = tp % 3, up = tp / 3;
            if (up >= 1) MBAR_WAIT(EMPTY + 8 * sp, (up - 1) & 1);
            MBAR_EXPECT_TX(FULL + 8 * sp, 32768u);
            tma_bulk(ST + sp * 32768,         A  + ((size_t)(bm * 64 + tp)) * 8192, 16384u, FULL + 8 * sp);
            tma_bulk(ST + sp * 32768 + 16384, Bw + ((size_t)(bn * 64 + tp)) * 8192, 16384u, FULL + 8 * sp);
        }
        MBAR_WAIT(FULL + 8 * s, (t / 3) & 1);
        const uint32_t st = ST + s * 32768;

#pragma unroll
        for (int kk = 0; kk < 32; kk += 16) {
            uint32_t ah[2][4], al[2][4];
#pragma unroll
            for (int mi = 0; mi < 2; mi++) {
                int rr = wm + mi * 16 + (lane & 15);
                int c8 = (kk >> 3) + (lane >> 4);
                int slot = c8 ^ ((rr >> 1) & 3);
                uint32_t ad = st + (uint32_t)(rr * 64 + slot * 16);
                LDSM4(ah[mi][0], ah[mi][1], ah[mi][2], ah[mi][3], ad);
                LDSM4(al[mi][0], al[mi][1], al[mi][2], al[mi][3], ad + 8192);
            }
#pragma unroll
            for (int n2 = 0; n2 < 4; n2++) {
                int rb = wn + n2 * 16 + (lane & 7) + ((lane & 16) ? 8 : 0);
                int c8 = (kk >> 3) + ((lane & 8) ? 1 : 0);
                int slot = c8 ^ ((rb >> 1) & 3);
                uint32_t bd = st + 16384 + (uint32_t)(rb * 64 + slot * 16);
                uint32_t bh[4], bl[4];
                LDSM4(bh[0], bh[1], bh[2], bh[3], bd);
                LDSM4(bl[0], bl[1], bl[2], bl[3], bd + 8192);
#pragma unroll
                for (int mi = 0; mi < 2; mi++) {
                    MMA_BF(acc[mi][2 * n2],     ah[mi], bh[0], bh[1]);
                    MMA_BF(acc[mi][2 * n2 + 1], ah[mi], bh[2], bh[3]);
                    MMA_BF(acc[mi][2 * n2],     al[mi], bh[0], bh[1]);
                    MMA_BF(acc[mi][2 * n2 + 1], al[mi], bh[2], bh[3]);
                    MMA_BF(acc[mi][2 * n2],     ah[mi], bl[0], bl[1]);
                    MMA_BF(acc[mi][2 * n2 + 1], ah[mi], bl[2], bl[3]);
                }
            }
        }
        if (lane == 0) MBAR_ARRIVE(EMPTY + 8 * s);
    }

#pragma unroll
    for (int mi = 0; mi < 2; mi++)
#pragma unroll
        for (int ni = 0; ni < 8; ni++) {
            int row = bm * 128 + wm + mi * 16 + (lane >> 2);
            int col = bn * 128 + wn + ni * 8 + (lane & 3) * 2;
            float* c = acc[mi][ni];
            C[(size_t)row * Cn + col]           = c[0];
            C[(size_t)row * Cn + col + 1]       = c[1];
            C[(size_t)(row + 8) * Cn + col]     = c[2];
            C[(size_t)(row + 8) * Cn + col + 1] = c[3];
        }
}

// ---------------- bulk-TMA fp16 single GEMM (out-proj): 16KB/stage, 6 stages ----------------
__global__ __launch_bounds__(256, 2)
void bgemm1(const __half* __restrict__ A, const __half* __restrict__ Bw,
            float* __restrict__ C)
{
    extern __shared__ __align__(1024) char smem[];
    const uint32_t sb = smem_u32(smem);
    const int tid = threadIdx.x, w = tid >> 5, lane = tid & 31;
    const int bn = blockIdx.x, bm = blockIdx.y;
    const int wm = (w & 3) * 32, wn = (w >> 2) * 64;

    const uint32_t FULL = sb;
    const uint32_t EMPTY = sb + 64;
    const uint32_t ST = sb + 1024;

    if (tid == 0) {
#pragma unroll
        for (int s = 0; s < 6; s++) { MBAR_INIT(FULL + 8 * s, 1); MBAR_INIT(EMPTY + 8 * s, 8); }
    }
    __syncthreads();

    if (tid == 0) {
#pragma unroll
        for (int t = 0; t < 5; t++) {
            MBAR_EXPECT_TX(FULL + 8 * t, 16384u);
            tma_bulk(ST + t * 16384,        A  + ((size_t)(bm * 64 + t)) * 4096, 8192u, FULL + 8 * t);
            tma_bulk(ST + t * 16384 + 8192, Bw + ((size_t)(bn * 64 + t)) * 4096, 8192u, FULL + 8 * t);
        }
    }

    float acc[2][8][4];
#pragma unroll
    for (int mi = 0; mi < 2; mi++)
#pragma unroll
        for (int ni = 0; ni < 8; ni++)
#pragma unroll
            for (int q = 0; q < 4; q++) acc[mi][ni][q] = 0.f;

    for (int t = 0; t < 64; t++) {
        int s = t % 6;
        if (tid == 0 && t + 5 < 64) {
            int tp = t + 5, sp = tp % 6, up = tp / 6;
            if (up >= 1) MBAR_WAIT(EMPTY + 8 * sp, (up - 1) & 1);
            MBAR_EXPECT_TX(FULL + 8 * sp, 16384u);
            tma_bulk(ST + sp * 16384,        A  + ((size_t)(bm * 64 + tp)) * 4096, 8192u, FULL + 8 * sp);
            tma_bulk(ST + sp * 16384 + 8192, Bw + ((size_t)(bn * 64 + tp)) * 4096, 8192u, FULL + 8 * sp);
        }
        MBAR_WAIT(FULL + 8 * s, (t / 6) & 1);
        const uint32_t st = ST + s * 16384;

#pragma unroll
        for (int kk = 0; kk < 32; kk += 16) {
            uint32_t af[2][4];
#pragma unroll
            for (int mi = 0; mi < 2; mi++) {
                int rr = wm + mi * 16 + (lane & 15);
                int c8 = (kk >> 3) + (lane >> 4);
                int slot = c8 ^ ((rr >> 1) & 3);
                LDSM4(af[mi][0], af[mi][1], af[mi][2], af[mi][3],
                      st + (uint32_t)(rr * 64 + slot * 16));
            }
#pragma unroll
            for (int n2 = 0; n2 < 4; n2++) {
                int rb = wn + n2 * 16 + (lane & 7) + ((lane & 16) ? 8 : 0);
                int c8 = (kk >> 3) + ((lane & 8) ? 1 : 0);
                int slot = c8 ^ ((rb >> 1) & 3);
                uint32_t bq[4];
                LDSM4(bq[0], bq[1], bq[2], bq[3],
                      st + 8192 + (uint32_t)(rb * 64 + slot * 16));
#pragma unroll
                for (int mi = 0; mi < 2; mi++) {
                    MMA_FP(acc[mi][2 * n2],     af[mi], bq[0], bq[1]);
                    MMA_FP(acc[mi][2 * n2 + 1], af[mi], bq[2], bq[3]);
                }
            }
        }
        if (lane == 0) MBAR_ARRIVE(EMPTY + 8 * s);
    }

#pragma unroll
    for (int mi = 0; mi < 2; mi++)
#pragma unroll
        for (int ni = 0; ni < 8; ni++) {
            int row = bm * 128 + wm + mi * 16 + (lane >> 2);
            int col = bn * 128 + wn + ni * 8 + (lane & 3) * 2;
            float* c = acc[mi][ni];
            C[(size_t)row * Cn + col]           = c[0];
            C[(size_t)row * Cn + col + 1]       = c[1];
            C[(size_t)(row + 8) * Cn + col]     = c[2];
            C[(size_t)(row + 8) * Cn + col + 1] = c[3];
        }
}

// ---------------- mma.sync split-bf16 GEMM for MLPs ----------------
template<int KA, int MODE>
__global__ __launch_bounds__(256, 2)
void hgemm(float* __restrict__ Cf, int ncols,
           const float* __restrict__ b0, const float* __restrict__ b1,
           const float* __restrict__ b2)
{
    constexpr int TPS = KA / 32;
    constexpr int KT  = 3 * TPS;
    constexpr int SSZ = 128 * 40;
    extern __shared__ bf16 sh[];
    bf16* As = sh;
    bf16* Bs = sh + 3 * SSZ;

    const int tid = threadIdx.x;
    const int z = blockIdx.z;
    const int bm = blockIdx.y * 128, bn = blockIdx.x * 128;
    const int w = tid >> 5, lane = tid & 31;
    const int wm = (w & 3) * 32, wn = (w >> 2) * 64;

    const bf16* A;
    const bf16* Bw;
    if (MODE == 6) {
        A = (z == 0) ? g_xw : (z == 1) ? g_xa : (z == 2) ? g_xvr : g_xg;
        Bw = g_w1t[z];
    } else {
        A = g_hid4[z];
        Bw = g_w2t[z];
    }

    float acc[2][8][4];
#pragma unroll
    for (int mi = 0; mi < 2; mi++)
#pragma unroll
        for (int ni = 0; ni < 8; ni++)
#pragma unroll
            for (int q = 0; q < 4; q++) acc[mi][ni][q] = 0.f;

    auto loadtile = [&](int stage, int t) {
        int seg = t / TPS, kk = (t % TPS) * 32;
        int aoff = (seg == 1 ? KA : 0) + kk;
        int boff = (seg == 2 ? KA : 0) + kk;
        bf16* as = As + stage * SSZ;
        bf16* bs = Bs + stage * SSZ;
#pragma unroll
        for (int c = 0; c < 2; c++) {
            int ch = tid + c * 256;
            int row = ch >> 2, col = ch & 3;
            unsigned sa = (unsigned)__cvta_generic_to_shared(&as[row * 40 + col * 8]);
            const void* ga = &A[(size_t)(bm + row) * (2 * KA) + aoff + col * 8];
            asm volatile("cp.async.cg.shared.global [%0], [%1], 16;\n" :: "r"(sa), "l"(ga));
            unsigned sb2 = (unsigned)__cvta_generic_to_shared(&bs[row * 40 + col * 8]);
            const void* gb = &Bw[(size_t)(bn + row) * (2 * KA) + boff + col * 8];
            asm volatile("cp.async.cg.shared.global [%0], [%1], 16;\n" :: "r"(sb2), "l"(gb));
        }
        asm volatile("cp.async.commit_group;\n" ::: "memory");
    };

    loadtile(0, 0);
    loadtile(1, 1);

    const int arow = wm + (lane & 15);
    const int acolo = (lane >> 4) << 3;
    const int brow = (lane & 7) + ((lane & 16) ? 8 : 0);
    const int bcolo = (lane & 8) ? 8 : 0;

    for (int t = 0; t < KT; t++) {
        if (t + 1 < KT) {
            asm volatile("cp.async.wait_group 1;\n" ::: "memory");
        } else {
            asm volatile("cp.async.wait_group 0;\n" ::: "memory");
        }
        __syncthreads();
        if (t + 2 < KT) loadtile((t + 2) % 3, t + 2);

        const bf16* as = As + (t % 3) * SSZ;
        const bf16* bs = Bs + (t % 3) * SSZ;
        unsigned abase = (unsigned)__cvta_generic_to_shared(as);
        unsigned bbase = (unsigned)__cvta_generic_to_shared(bs);

#pragma unroll
        for (int kk = 0; kk < 32; kk += 16) {
            uint32_t af[2][4];
#pragma unroll
            for (int mi = 0; mi < 2; mi++) {
                unsigned aaddr = abase + (unsigned)(((arow + mi * 16) * 40 + kk + acolo) * 2);
                LDSM4(af[mi][0], af[mi][1], af[mi][2], af[mi][3], aaddr);
            }
            uint32_t bq[4][4];
#pragma unroll
            for (int n2 = 0; n2 < 4; n2++) {
                unsigned baddr = bbase + (unsigned)(((wn + n2 * 16 + brow) * 40 + kk + bcolo) * 2);
                LDSM4(bq[n2][0], bq[n2][1], bq[n2][2], bq[n2][3], baddr);
            }
#pragma unroll
            for (int n2 = 0; n2 < 4; n2++) {
#pragma unroll
                for (int mi = 0; mi < 2; mi++) {
                    MMA_BF(acc[mi][2 * n2],     af[mi], bq[n2][0], bq[n2][1]);
                    MMA_BF(acc[mi][2 * n2 + 1], af[mi], bq[n2][2], bq[n2][3]);
                }
            }
        }
        __syncthreads();
    }

#pragma unroll
    for (int mi = 0; mi < 2; mi++)
#pragma unroll
        for (int ni = 0; ni < 8; ni++) {
            int row = bm + wm + mi * 16 + (lane >> 2);
            int col = bn + wn + ni * 8 + (lane & 3) * 2;
            float* c = acc[mi][ni];
            if (MODE == 6) {
                bf16* hid = g_hid4[z];
                auto act = [&](float v) -> float {
                    if (z == 0) return tanhf(v);
                    if (z == 3) return 1.f / (1.f + expf(-v));
                    return v;
                };
                split_store(hid, (size_t)row * 256 + col,           KP, act(c[0]));
                split_store(hid, (size_t)row * 256 + col + 1,       KP, act(c[1]));
                split_store(hid, (size_t)(row + 8) * 256 + col,     KP, act(c[2]));
                split_store(hid, (size_t)(row + 8) * 256 + col + 1, KP, act(c[3]));
            } else {
                float* dst = (z == 0) ? g_wdec : (z == 1) ? g_a : (z == 2) ? g_vg : g_g;
                auto epi = [&](float v, int n) -> float {
                    if (z == 0) return expf(-0.60653066f / (1.f + expf(-(b0[n] + v))));
                    if (z == 1) return 1.f / (1.f + expf(-(b1[n] + v)));
                    if (z == 2) return 1.f / (1.f + expf(-(b2[n] + v)));
                    return v;
                };
                dst[(size_t)row * Cn + col]           = epi(c[0], col);
                dst[(size_t)row * Cn + col + 1]       = epi(c[1], col + 1);
                dst[(size_t)(row + 8) * Cn + col]     = epi(c[2], col);
                dst[(size_t)(row + 8) * Cn + col + 1] = epi(c[3], col + 1);
            }
        }
}

// ---------------- fused: v-combine + kk-normalize + k-update ----------------
__global__ __launch_bounds__(256)
void kkv_fused(const float* __restrict__ vf, const float* __restrict__ mask,
               const float* __restrict__ kkw, const float* __restrict__ kaw)
{
    const int warp = threadIdx.x >> 5, lane = threadIdx.x & 31;
    const int gid = blockIdx.x * 8 + warp;
    const int h = gid & (Hn - 1);
    const int bt = gid >> 5;
    size_t base = (size_t)gid * 64;
    int c0 = h * 64 + lane, c1 = c0 + 32;
    float m = mask[bt];

    float v0v = g_v[base + lane], v1v = g_v[base + lane + 32];
    float gt0 = g_vg[base + lane], gt1 = g_vg[base + lane + 32];
    v0v = (v0v + (vf[base + lane] - v0v) * gt0) * m;
    v1v = (v1v + (vf[base + lane + 32] - v1v) * gt1) * m;
    g_v[base + lane] = v0v;
    g_v[base + lane + 32] = v1v;

    float k0v = g_k[base + lane], k1v = g_k[base + lane + 32];
    float kk0 = k0v * kkw[c0], kk1 = k1v * kkw[c1];
    float ss = kk0 * kk0 + kk1 * kk1;
#pragma unroll
    for (int off = 16; off > 0; off >>= 1) ss += __shfl_xor_sync(0xffffffffu, ss, off);
    float inv = 1.f / fmaxf(sqrtf(ss), 1e-12f);
    float a0v = g_a[base + lane], a1v = g_a[base + lane + 32];
    g_nkk[base + lane]      = -kk0 * inv;
    g_nkk[base + lane + 32] = -kk1 * inv;
    g_ab[base + lane]       = kk0 * inv * a0v;
    g_ab[base + lane + 32]  = kk1 * inv * a1v;
    g_knew[base + lane]      = k0v * (1.f + (a0v - 1.f) * kaw[c0]);
    g_knew[base + lane + 32] = k1v * (1.f + (a1v - 1.f) * kaw[c1]);
}

// ---------------- RWKV-7 scan: 128 threads, 2 per state row, 4-way accumulators ----------------
__global__ __launch_bounds__(128)
void scan_kernel()
{
    const int bh = blockIdx.x;
    const int b = bh >> 5, h = bh & 31;
    const int tid = threadIdx.x;
    const int j = tid >> 1, half = tid & 1;
    size_t base = (size_t)b * Tn * Cn + h * 64;

    float S[32];
#pragma unroll
    for (int i = 0; i < 32; i++) S[i] = 0.f;

    __shared__ float sm[2][384];

    const float* gsrc0;
    const float* gsrc1;
    const float* gsrc2;
    {
        const float* tbl[6] = {g_r, g_wdec, g_knew, g_v, g_nkk, g_ab};
        int l0 = tid, l1 = tid + 128, l2 = tid + 256;
        gsrc0 = tbl[l0 >> 6] + base + (l0 & 63);
        gsrc1 = tbl[l1 >> 6] + base + (l1 & 63);
        gsrc2 = tbl[l2 >> 6] + base + (l2 & 63);
    }
    float f0 = *gsrc0, f1 = *gsrc1, f2 = *gsrc2;

    for (int t = 0; t < Tn; t++) {
        float* sb = sm[t & 1];
        sb[tid] = f0; sb[tid + 128] = f1; sb[tid + 256] = f2;
        __syncthreads();

        if (t + 1 < Tn) {
            gsrc0 += Cn; gsrc1 += Cn; gsrc2 += Cn;
            f0 = *gsrc0; f1 = *gsrc1; f2 = *gsrc2;
        }

        const float* rv = sb + half * 32;
        const float* wv = sb + 64 + half * 32;
        const float* kv = sb + 128 + half * 32;
        const float* av = sb + 256 + half * 32;
        const float* bv = sb + 320 + half * 32;

        float sa0 = 0.f, sa1 = 0.f, sa2 = 0.f, sa3 = 0.f;
#pragma unroll
        for (int ii = 0; ii < 32; ii += 4) {
            sa0 = fmaf(S[ii],     av[ii],     sa0);
            sa1 = fmaf(S[ii + 1], av[ii + 1], sa1);
            sa2 = fmaf(S[ii + 2], av[ii + 2], sa2);
            sa3 = fmaf(S[ii + 3], av[ii + 3], sa3);
        }
        float sa = (sa0 + sa1) + (sa2 + sa3);
        sa += __shfl_xor_sync(0xffffffffu, sa, 1);

        float vj = sb[192 + j];
        float y0 = 0.f, y1 = 0.f, y2 = 0.f, y3 = 0.f;
#pragma unroll
        for (int ii = 0; ii < 32; ii += 4) {
            S[ii]     = fmaf(S[ii],     wv[ii],     fmaf(sa, bv[ii],     vj * kv[ii]));
            S[ii + 1] = fmaf(S[ii + 1], wv[ii + 1], fmaf(sa, bv[ii + 1], vj * kv[ii + 1]));
            S[ii + 2] = fmaf(S[ii + 2], wv[ii + 2], fmaf(sa, bv[ii + 2], vj * kv[ii + 2]));
            S[ii + 3] = fmaf(S[ii + 3], wv[ii + 3], fmaf(sa, bv[ii + 3], vj * kv[ii + 3]));
            y0 = fmaf(S[ii],     rv[ii],     y0);
            y1 = fmaf(S[ii + 1], rv[ii + 1], y1);
            y2 = fmaf(S[ii + 2], rv[ii + 2], y2);
            y3 = fmaf(S[ii + 3], rv[ii + 3], y3);
        }
        float y = (y0 + y1) + (y2 + y3);
        y += __shfl_xor_sync(0xffffffffu, y, 1);
        if (!half) g_y[base + (size_t)t * Cn + j] = y;
    }
}

// ---------------- groupnorm + rk bonus + gate -> fp16 tiled ----------------
__global__ __launch_bounds__(128)
void postln_kernel(const float* __restrict__ rkw, const float* __restrict__ lnw,
                   const float* __restrict__ lnb)
{
    const int warp = threadIdx.x >> 5, lane = threadIdx.x & 31;
    const int gid = blockIdx.x * 4 + warp;
    const int h = gid & (Hn - 1);
    const int bt = gid >> 5;
    size_t base = (size_t)gid * 64;
    int c0 = h * 64 + lane, c1 = c0 + 32;

    float y0 = g_y[base + lane], y1 = g_y[base + lane + 32];
    float s = y0 + y1;
#pragma unroll
    for (int off = 16; off > 0; off >>= 1) s += __shfl_xor_sync(0xffffffffu, s, off);
    float mu = s * (1.f / 64.f);
    float d0 = y0 - mu, d1 = y1 - mu;
    float vs = d0 * d0 + d1 * d1;
#pragma unroll
    for (int off = 16; off > 0; off >>= 1) vs += __shfl_xor_sync(0xffffffffu, vs, off);
    float inv = rsqrtf(vs * (1.f / 64.f) + LN_EPS);

    float rk = g_r[base + lane] * g_knew[base + lane] * rkw[c0]
             + g_r[base + lane + 32] * g_knew[base + lane + 32] * rkw[c1];
#pragma unroll
    for (int off = 16; off > 0; off >>= 1) rk += __shfl_xor_sync(0xffffffffu, rk, off);

    float yn0 = d0 * inv * lnw[c0] + lnb[c0];
    float yn1 = d1 * inv * lnw[c1] + lnb[c1];
    float o0 = (yn0 + rk * g_v[base + lane])      * g_g[base + lane];
    float o1 = (yn1 + rk * g_v[base + lane + 32]) * g_g[base + lane + 32];

    int mb = bt >> 7, r = bt & 127;
    g_ygt[tile_idx4(mb, c0 >> 5, r, c0 & 31)] = __float2half(o0);
    g_ygt[tile_idx4(mb, c1 >> 5, r, c1 & 31)] = __float2half(o1);
}

// ---------------- host ----------------
template<typename T> static T* sym(const void* s) { void* p = nullptr; cudaGetSymbolAddress(&p, s); return (T*)p; }

extern "C" void kernel_launch(void* const* d_in, const int* in_sizes, int n_in,
                              void* d_out, int out_size)
{
    const float* x    = (const float*)d_in[0];
    const float* mask = (const float*)d_in[1];
    const float* vf   = (const float*)d_in[2];
    const float* x_r  = (const float*)d_in[3];
    const float* x_w  = (const float*)d_in[4];
    const float* x_k  = (const float*)d_in[5];
    const float* x_v  = (const float*)d_in[6];
    const float* x_a  = (const float*)d_in[7];
    const float* x_g  = (const float*)d_in[8];
    const float* w0   = (const float*)d_in[9];
    const float* w1   = (const float*)d_in[10];
    const float* w2   = (const float*)d_in[11];
    const float* a0   = (const float*)d_in[12];
    const float* a1   = (const float*)d_in[13];
    const float* a2   = (const float*)d_in[14];
    const float* v0   = (const float*)d_in[15];
    const float* v1   = (const float*)d_in[16];
    const float* v2   = (const float*)d_in[17];
    const float* g1   = (const float*)d_in[18];
    const float* g2   = (const float*)d_in[19];
    const float* k_k  = (const float*)d_in[20];
    const float* k_a  = (const float*)d_in[21];
    const float* r_k  = (const float*)d_in[22];
    const float* W_r  = (const float*)d_in[23];
    const float* W_k  = (const float*)d_in[24];
    const float* W_v  = (const float*)d_in[25];
    const float* W_o  = (const float*)d_in[26];
    const float* ln_w = (const float*)d_in[27];
    const float* ln_b = (const float*)d_in[28];

    __half* p_Wo16 = sym<__half>(g_Wo16);
    __half* p_ygt  = sym<__half>(g_ygt);

    float* out = (float*)d_out;

    const unsigned EW = (unsigned)((BTC + 255) / 256);
    const unsigned WW = (unsigned)(((size_t)Cn * Cn + 255) / 256);
    const unsigned TW = (unsigned)((KP * Cn + 255) / 256);
    const int SHB = 3 * 128 * 40 * 2 * 2;       // hgemm smem (61440)
    const int BSH3 = 1024 + 3 * 32768;          // bgemm3 smem (99328)
    const int BSH1 = 1024 + 6 * 16384;          // bgemm1 smem (99328)

    cudaFuncSetAttribute(hgemm<2048, 6>, cudaFuncAttributeMaxDynamicSharedMemorySize, SHB);
    cudaFuncSetAttribute(hgemm<128, 7>,  cudaFuncAttributeMaxDynamicSharedMemorySize, SHB);
    cudaFuncSetAttribute(bgemm3, cudaFuncAttributeMaxDynamicSharedMemorySize, BSH3);
    cudaFuncSetAttribute(bgemm1, cudaFuncAttributeMaxDynamicSharedMemorySize, BSH1);

    // weight prep (batched)
    conv_wt4<<<dim3(WW, 4), 256>>>(W_r, W_k, W_v, W_o);
    tsplit1_4<<<dim3(TW, 4), 256>>>(w1, a1, v1, g1);
    tsplit2_4<<<dim3(TW, 4), 256>>>(w2, a2, v2, g2);

    // mixing
    mix_split<<<EW, 256>>>(x, mask, x_r, x_w, x_k, x_v, x_a, x_g);

    // batched mlp1 (4 paths) on mma.sync (split-bf16)
    hgemm<2048, 6><<<dim3(1, 64, 4), 256, SHB>>>(nullptr, 128, nullptr, nullptr, nullptr);

    // big projections r/k/v: bf16 3-term bulk-TMA GEMM
    bgemm3<<<dim3(16, 64, 3), 256, BSH3>>>();

    // batched mlp2 (4 paths)
    hgemm<128, 7><<<dim3(16, 64, 4), 256, SHB>>>(nullptr, Cn, w0, a0, v0);

    // fused v-combine + kk
    kkv_fused<<<BT * Hn / 8, 256>>>(vf, mask, k_k, k_a);

    // scan
    scan_kernel<<<Bn * Hn, 128>>>();

    // post groupnorm -> fp16 tiled
    postln_kernel<<<BT * Hn / 4, 128>>>(r_k, ln_w, ln_b);

    // output projection: single fp16 (post-amplification, error ~4e-4 direct)
    bgemm1<<<dim3(16, 64, 1), 256, BSH1>>>(p_ygt, p_Wo16, out);

    if ((size_t)out_size >= 2 * BTC) {
        cudaMemcpyAsync(out + BTC, vf, BTC * sizeof(float), cudaMemcpyDeviceToDevice, 0);
    }
}